// round 1
// baseline (speedup 1.0000x reference)
#include <cuda_runtime.h>
#include <math.h>

// Problem constants
#define NFEAT 16384          // B*H*W = 16*32*32
#define KCODE 8192           // codebook size
#define CDIM  256            // codebook dim
#define BATCH 16
#define HDIM  32
#define WDIM  32

// Output layout (float32, concatenated in reference tuple order)
#define OUT_ZQ    0
#define OUT_LOSS  4194304
#define OUT_QERR  4194305
#define OUT_UTIL  4194306
#define OUT_PERP  4194307
#define OUT_NEMB  4194308
#define OUT_NPROB 6291460

// Scratch (device globals; no dynamic allocation allowed)
__device__ float              g_zf[NFEAT * CDIM];   // transposed features (N,C), 16MB
__device__ float              g_S[NFEAT];           // ||zf||^2 per row
__device__ float              g_e2[KCODE];          // ||e||^2 per code
__device__ unsigned long long g_minkey[NFEAT];      // argmin keys (value<<32 | j)
__device__ unsigned long long g_maxkey[KCODE];      // argmax keys (~value<<32 | n)
__device__ unsigned int       g_hist[KCODE];
__device__ int                g_token[NFEAT];
__device__ int                g_far[KCODE];
__device__ float              g_sse;
__device__ float              g_ent;
__device__ unsigned int       g_util;

__device__ __forceinline__ unsigned int ford(float f) {
    unsigned int u = __float_as_uint(f);
    return (u & 0x80000000u) ? ~u : (u | 0x80000000u);
}

// ---------------------------------------------------------------------------
// K0: init scratch
// ---------------------------------------------------------------------------
__global__ void init_kernel() {
    int i = blockIdx.x * blockDim.x + threadIdx.x;
    if (i < NFEAT) g_minkey[i] = ~0ull;
    if (i < KCODE) { g_maxkey[i] = ~0ull; g_hist[i] = 0u; }
    if (i == 0) { g_sse = 0.0f; g_ent = 0.0f; g_util = 0u; }
}

// ---------------------------------------------------------------------------
// K1: transpose z (B,C,H,W) -> zf (N,C), compute S_n = sum_c zf^2
// One block per (b,h): 32 w x 256 c tile staged through SMEM.
// ---------------------------------------------------------------------------
__global__ void __launch_bounds__(256) prep_kernel(const float* __restrict__ z) {
    __shared__ float tile[32][CDIM + 1];
    int tid = threadIdx.x;
    int tx = tid & 31, ty = tid >> 5;       // lane, warp
    int b = blockIdx.x >> 5, h = blockIdx.x & 31;
    const float* zp = z + (size_t)b * (CDIM * HDIM * WDIM) + h * WDIM;
    // load: lane=w coalesced, c = i*8+ty
#pragma unroll
    for (int i = 0; i < 32; i++) {
        int c = i * 8 + ty;
        tile[tx][c] = zp[c * (HDIM * WDIM) + tx];
    }
    __syncthreads();
    int nbase = b * 1024 + h * 32;
    // each warp handles 4 rows (w); write zf coalesced + compute S
#pragma unroll
    for (int j = 0; j < 4; j++) {
        int w = ty * 4 + j;
        int n = nbase + w;
        float s = 0.0f;
#pragma unroll
        for (int i = 0; i < 8; i++) {
            int c = tx + 32 * i;
            float v = tile[w][c];
            g_zf[(size_t)n * CDIM + c] = v;
            s += v * v;
        }
#pragma unroll
        for (int m = 16; m; m >>= 1) s += __shfl_xor_sync(0xffffffffu, s, m);
        if (tx == 0) g_S[n] = s;
    }
}

// ---------------------------------------------------------------------------
// K2: e2_j = sum_c e^2 (one warp per code row, 8 rows per block)
// ---------------------------------------------------------------------------
__global__ void __launch_bounds__(256) e2_kernel(const float* __restrict__ emb) {
    int tid = threadIdx.x;
    int tx = tid & 31, ty = tid >> 5;
    int j = blockIdx.x * 8 + ty;
    float s = 0.0f;
#pragma unroll
    for (int i = 0; i < 8; i++) {
        float v = emb[(size_t)j * CDIM + tx + 32 * i];
        s += v * v;
    }
#pragma unroll
    for (int m = 16; m; m >>= 1) s += __shfl_xor_sync(0xffffffffu, s, m);
    if (tx == 0) g_e2[j] = s;
}

// ---------------------------------------------------------------------------
// K3: fused fp32 GEMM (dot = zf @ emb^T) + d formation + argmin/argmax.
// 128x128 CTA tile, K=256, BK=8, 256 threads, 8x8 micro-tile per thread.
// Inner product built from fma.rn.f32x2 (packed FFMA2, 2x fp32 throughput).
// Accumulator pairs along N; B duplicated to float2 in SMEM.
// Column mapping j = tx + 16*q keeps LDS.64 of B conflict-free.
// ---------------------------------------------------------------------------
#define BN 128
#define BJ 128
#define BK 8

__global__ void __launch_bounds__(256, 2) gemm_kernel(const float* __restrict__ emb) {
    __shared__ __align__(16) float  As[2][BK * BN];   // [k][n]
    __shared__ __align__(16) float2 Bs[2][BK * BJ];   // [k][j], value duplicated
    __shared__ unsigned long long colkey[BJ];

    int tid = threadIdx.x;
    int tx = tid & 15, ty = tid >> 4;
    int n0 = blockIdx.y * BN;
    int j0 = blockIdx.x * BJ;
    if (tid < BJ) colkey[tid] = ~0ull;

    int arow = tid >> 1;
    int acg  = (tid & 1) * 4;
    const float* gA = g_zf + (size_t)(n0 + arow) * CDIM + acg;
    const float* gB = emb  + (size_t)(j0 + arow) * CDIM + acg;

    float4 ra = *(const float4*)gA;
    float4 rb = *(const float4*)gB;
    {
        float*  a0 = As[0];
        float2* b0 = Bs[0];
        a0[(acg + 0) * BN + arow] = ra.x;
        a0[(acg + 1) * BN + arow] = ra.y;
        a0[(acg + 2) * BN + arow] = ra.z;
        a0[(acg + 3) * BN + arow] = ra.w;
        b0[(acg + 0) * BJ + arow] = make_float2(rb.x, rb.x);
        b0[(acg + 1) * BJ + arow] = make_float2(rb.y, rb.y);
        b0[(acg + 2) * BJ + arow] = make_float2(rb.z, rb.z);
        b0[(acg + 3) * BJ + arow] = make_float2(rb.w, rb.w);
    }
    __syncthreads();

    unsigned long long acc[32];
#pragma unroll
    for (int i = 0; i < 32; i++) acc[i] = 0ull;

#pragma unroll 1
    for (int kb = 0; kb < CDIM / BK; kb++) {
        int cur = kb & 1;
        if (kb + 1 < CDIM / BK) {
            ra = *(const float4*)(gA + (kb + 1) * BK);
            rb = *(const float4*)(gB + (kb + 1) * BK);
        }
        const unsigned long long* A64 = (const unsigned long long*)As[cur];
        const unsigned long long* B64 = (const unsigned long long*)Bs[cur];
#pragma unroll
        for (int k = 0; k < BK; k++) {
            unsigned long long a[4], b[8];
#pragma unroll
            for (int p = 0; p < 4; p++) a[p] = A64[k * (BN / 2) + ty * 4 + p];
#pragma unroll
            for (int q = 0; q < 8; q++) b[q] = B64[k * BJ + tx + 16 * q];
#pragma unroll
            for (int p = 0; p < 4; p++) {
#pragma unroll
                for (int q = 0; q < 8; q++) {
                    asm("fma.rn.f32x2 %0, %1, %2, %0;"
                        : "+l"(acc[p * 8 + q]) : "l"(a[p]), "l"(b[q]));
                }
            }
        }
        if (kb + 1 < CDIM / BK) {
            int nxt = cur ^ 1;
            float*  an = As[nxt];
            float2* bn = Bs[nxt];
            an[(acg + 0) * BN + arow] = ra.x;
            an[(acg + 1) * BN + arow] = ra.y;
            an[(acg + 2) * BN + arow] = ra.z;
            an[(acg + 3) * BN + arow] = ra.w;
            bn[(acg + 0) * BJ + arow] = make_float2(rb.x, rb.x);
            bn[(acg + 1) * BJ + arow] = make_float2(rb.y, rb.y);
            bn[(acg + 2) * BJ + arow] = make_float2(rb.z, rb.z);
            bn[(acg + 3) * BJ + arow] = make_float2(rb.w, rb.w);
            __syncthreads();
        }
    }

    // Epilogue: d = fl( fl(S + e2) - 2*dot ), reduce argmin per row / argmax per col
    float Sv[8], E2[8];
#pragma unroll
    for (int r = 0; r < 8; r++) Sv[r] = g_S[n0 + ty * 8 + r];
#pragma unroll
    for (int q = 0; q < 8; q++) E2[q] = g_e2[j0 + tx + 16 * q];

    unsigned long long rkey[8], ckey[8];
#pragma unroll
    for (int r = 0; r < 8; r++) rkey[r] = ~0ull;
#pragma unroll
    for (int q = 0; q < 8; q++) ckey[q] = ~0ull;

#pragma unroll
    for (int p = 0; p < 4; p++) {
        unsigned nA = (unsigned)(n0 + ty * 8 + 2 * p);
        unsigned nB = nA + 1;
#pragma unroll
        for (int q = 0; q < 8; q++) {
            unsigned long long v = acc[p * 8 + q];
            float dot0 = __uint_as_float((unsigned)(v & 0xffffffffull));
            float dot1 = __uint_as_float((unsigned)(v >> 32));
            float d0 = fmaf(-2.0f, dot0, Sv[2 * p]     + E2[q]);
            float d1 = fmaf(-2.0f, dot1, Sv[2 * p + 1] + E2[q]);
            unsigned jj = (unsigned)(j0 + tx + 16 * q);
            unsigned long long k0 = ((unsigned long long)ford(d0) << 32) | jj;
            unsigned long long k1 = ((unsigned long long)ford(d1) << 32) | jj;
            rkey[2 * p]     = min(rkey[2 * p], k0);
            rkey[2 * p + 1] = min(rkey[2 * p + 1], k1);
            unsigned long long c0 = ((unsigned long long)(~ford(d0)) << 32) | nA;
            unsigned long long c1 = ((unsigned long long)(~ford(d1)) << 32) | nB;
            unsigned long long cm = min(c0, c1);
            ckey[q] = min(ckey[q], cm);
        }
    }
    // row-min reduce across tx (lane bits 0..3)
#pragma unroll
    for (int r = 0; r < 8; r++) {
        unsigned long long k = rkey[r];
#pragma unroll
        for (int m = 1; m < 16; m <<= 1)
            k = min(k, __shfl_xor_sync(0xffffffffu, k, m));
        if (tx == 0) atomicMin(&g_minkey[n0 + ty * 8 + r], k);
    }
    // col-max reduce across ty via SMEM atomics
#pragma unroll
    for (int q = 0; q < 8; q++) atomicMin(&colkey[tx + 16 * q], ckey[q]);
    __syncthreads();
    if (tid < BJ) atomicMin(&g_maxkey[j0 + tid], colkey[tid]);
}

// ---------------------------------------------------------------------------
// K4: extract tokens / far indices, build histogram
// ---------------------------------------------------------------------------
__global__ void token_kernel() {
    int i = blockIdx.x * blockDim.x + threadIdx.x;
    if (i < NFEAT) {
        unsigned tok = (unsigned)(g_minkey[i] & 0xffffffffull);
        g_token[i] = (int)tok;
        atomicAdd(&g_hist[tok], 1u);
    }
    if (i < KCODE) g_far[i] = (int)(g_maxkey[i] & 0xffffffffull);
}

// ---------------------------------------------------------------------------
// K5: z_q straight-through output (transposed back) + SSE reduction
// One block per (b,h); gather 32 embedding rows, write (c,w) coalesced.
// ---------------------------------------------------------------------------
__global__ void __launch_bounds__(256) zq_kernel(const float* __restrict__ emb,
                                                 float* __restrict__ out) {
    __shared__ float rowbuf[32][CDIM + 1];
    __shared__ int stok[32];
    __shared__ float red[8];
    int tid = threadIdx.x;
    int b = blockIdx.x >> 5, h = blockIdx.x & 31;
    int nbase = b * 1024 + h * 32;
    if (tid < 32) stok[tid] = g_token[nbase + tid];
    __syncthreads();
    float acc = 0.0f;
#pragma unroll 4
    for (int w = 0; w < 32; w++) {
        float v  = emb[(size_t)stok[w] * CDIM + tid];
        float zv = g_zf[(size_t)(nbase + w) * CDIM + tid];
        float diff = __fsub_rn(v, zv);
        acc = fmaf(diff, diff, acc);
        rowbuf[w][tid] = __fadd_rn(zv, diff);   // zp + (z_q - zp), reference rounding
    }
    float s = acc;
#pragma unroll
    for (int m = 16; m; m >>= 1) s += __shfl_xor_sync(0xffffffffu, s, m);
    if ((tid & 31) == 0) red[tid >> 5] = s;
    __syncthreads();
    if (tid == 0) {
        float t = 0.0f;
#pragma unroll
        for (int i = 0; i < 8; i++) t += red[i];
        atomicAdd(&g_sse, t);
    }
    int tx = tid & 31, ty = tid >> 5;
#pragma unroll
    for (int i = 0; i < 32; i++) {
        int c = i * 8 + ty;
        out[OUT_ZQ + (((size_t)b * CDIM + c) * HDIM + h) * WDIM + tx] = rowbuf[tx][c];
    }
}

// ---------------------------------------------------------------------------
// K6: per-code update: new_embed_prob, decay, new_embedding, entropy, util
// ---------------------------------------------------------------------------
__global__ void __launch_bounds__(256) code_kernel(const float* __restrict__ emb,
                                                   const float* __restrict__ eprob,
                                                   float* __restrict__ out) {
    int j = blockIdx.x;
    int c = threadIdx.x;
    unsigned hcnt = g_hist[j];
    float avg = (float)hcnt * (1.0f / 16384.0f);                  // exact pow2 div
    float np  = __fadd_rn(__fmul_rn(eprob[j], 0.99f), __fmul_rn(avg, 0.01f));
    float t = __fmul_rn(np, 8192.0f);
    t = __fmul_rn(t, 10.0f);
    t = __fdiv_rn(t, 0.01f);
    float decay = expf(-t - 0.001f);
    float omd = __fsub_rn(1.0f, decay);
    if (c == 0) {
        out[OUT_NPROB + j] = np;
        atomicAdd(&g_ent, avg * logf(avg + 1e-10f));
        if (hcnt > 0) atomicAdd(&g_util, 1u);
    }
    int fi = g_far[j];
    float rf = g_zf[(size_t)fi * CDIM + c];
    float e  = emb[(size_t)j * CDIM + c];
    out[OUT_NEMB + (size_t)j * CDIM + c] =
        __fadd_rn(__fmul_rn(e, omd), __fmul_rn(rf, decay));
}

// ---------------------------------------------------------------------------
// K7: finalize scalars
// ---------------------------------------------------------------------------
__global__ void fin_kernel(float* __restrict__ out) {
    float sse = g_sse;
    float mse = sse / 4194304.0f;                 // exact pow2 div
    out[OUT_LOSS] = __fadd_rn(__fmul_rn(0.25f, mse), mse);
    out[OUT_QERR] = sse / 16384.0f;
    out[OUT_UTIL] = (float)g_util / 8192.0f;
    out[OUT_PERP] = expf(-g_ent);
}

// ---------------------------------------------------------------------------
extern "C" void kernel_launch(void* const* d_in, const int* in_sizes, int n_in,
                              void* d_out, int out_size) {
    (void)in_sizes; (void)n_in; (void)out_size;
    const float* z     = (const float*)d_in[0];
    const float* emb   = (const float*)d_in[1];
    const float* eprob = (const float*)d_in[2];
    float* out = (float*)d_out;

    init_kernel<<<64, 256>>>();
    prep_kernel<<<BATCH * HDIM, 256>>>(z);
    e2_kernel<<<KCODE / 8, 256>>>(emb);
    gemm_kernel<<<dim3(KCODE / BJ, NFEAT / BN), 256>>>(emb);
    token_kernel<<<NFEAT / 256, 256>>>();
    zq_kernel<<<BATCH * HDIM, 256>>>(emb, out);
    code_kernel<<<KCODE, 256>>>(emb, eprob, out);
    fin_kernel<<<1, 1>>>(out);
}

// round 4
// speedup vs baseline: 1.9891x; 1.9891x over previous
#include <cuda_runtime.h>
#include <math.h>
#include <stdint.h>

// Problem constants
#define NFEAT 16384          // B*H*W = 16*32*32
#define KCODE 8192           // codebook size
#define CDIM  256            // codebook dim
#define BATCH 16
#define HDIM  32
#define WDIM  32

// Output layout (float32, concatenated in reference tuple order)
#define OUT_ZQ    0
#define OUT_LOSS  4194304
#define OUT_QERR  4194305
#define OUT_UTIL  4194306
#define OUT_PERP  4194307
#define OUT_NEMB  4194308
#define OUT_NPROB 6291460

// GEMM tiling
#define BM 128
#define BN 256
#define NJB (KCODE / BN)     // 32 j-blocks
#define BK 32
#define LDK 36
#define ROWB (LDK * 4)

// candidate window: must exceed 2*ulp(256) + 2*tf32_err  (~4.1e-5)
#define EPSB 8e-5f
#define MAXX (1 << 21)       // extras capacity (2M)

// Scratch (device globals; no dynamic allocation allowed)
__device__ float              g_zf[NFEAT * CDIM];
__device__ float              g_S[NFEAT];
__device__ float              g_e2[KCODE];
__device__ unsigned long long g_blockmin[NFEAT][NJB]; // per (row, jblock) min key
__device__ unsigned long long g_exkey[NFEAT];         // exact keys for contested rows
__device__ unsigned int       g_extras[MAXX];         // packed (n<<13)|j
__device__ unsigned int       g_xcnt;
__device__ unsigned long long g_maxkey[KCODE];
__device__ unsigned int       g_hist[KCODE];
__device__ int                g_token[NFEAT];
__device__ int                g_far[KCODE];
__device__ float              g_sse;
__device__ float              g_ent;
__device__ unsigned int       g_util;

__device__ __forceinline__ unsigned int ford(float f) {
    unsigned int u = __float_as_uint(f);
    return u ^ ((((int)u) >> 31) | 0x80000000u);
}
__device__ __forceinline__ float unford(unsigned int u) {
    unsigned int v = (u & 0x80000000u) ? (u ^ 0x80000000u) : ~u;
    return __uint_as_float(v);
}

// exact distance on the reference fp32 grid: dot in double, then
// d32 = fl32( fl32(S+e2) - 2*fl32(dot) ).  Warp-cooperative; all lanes return same.
__device__ __forceinline__ float exact_d32(const float* __restrict__ emb,
                                           int n, int j, int lane) {
    const float* zr = g_zf + (size_t)n * CDIM;
    const float* er = emb + (size_t)j * CDIM;
    double dd = 0.0;
#pragma unroll
    for (int c = 0; c < CDIM / 32; c++)
        dd += (double)zr[lane + 32 * c] * (double)er[lane + 32 * c];
#pragma unroll
    for (int m = 16; m; m >>= 1) dd += __shfl_xor_sync(0xffffffffu, dd, m);
    float dotf = (float)dd;
    return __fsub_rn(__fadd_rn(g_S[n], g_e2[j]), 2.0f * dotf);
}

// ---------------------------------------------------------------------------
// K0: init scratch
// ---------------------------------------------------------------------------
__global__ void init_kernel() {
    int i = blockIdx.x * blockDim.x + threadIdx.x;
    if (i < NFEAT) g_exkey[i] = ~0ull;
    if (i < KCODE) { g_maxkey[i] = ~0ull; g_hist[i] = 0u; }
    if (i == 0) { g_sse = 0.0f; g_ent = 0.0f; g_util = 0u; g_xcnt = 0u; }
}

// ---------------------------------------------------------------------------
// K1: transpose z (B,C,H,W) -> zf (N,C), compute S_n = sum_c zf^2
// ---------------------------------------------------------------------------
__global__ void __launch_bounds__(256) prep_kernel(const float* __restrict__ z) {
    __shared__ float tile[32][CDIM + 1];
    int tid = threadIdx.x;
    int tx = tid & 31, ty = tid >> 5;
    int b = blockIdx.x >> 5, h = blockIdx.x & 31;
    const float* zp = z + (size_t)b * (CDIM * HDIM * WDIM) + h * WDIM;
#pragma unroll
    for (int i = 0; i < 32; i++) {
        int c = i * 8 + ty;
        tile[tx][c] = zp[c * (HDIM * WDIM) + tx];
    }
    __syncthreads();
    int nbase = b * 1024 + h * 32;
#pragma unroll
    for (int j = 0; j < 4; j++) {
        int w = ty * 4 + j;
        int n = nbase + w;
        float s = 0.0f;
#pragma unroll
        for (int i = 0; i < 8; i++) {
            int c = tx + 32 * i;
            float v = tile[w][c];
            g_zf[(size_t)n * CDIM + c] = v;
            s += v * v;
        }
#pragma unroll
        for (int m = 16; m; m >>= 1) s += __shfl_xor_sync(0xffffffffu, s, m);
        if (tx == 0) g_S[n] = s;
    }
}

// ---------------------------------------------------------------------------
// K2: e2_j = sum_c e^2
// ---------------------------------------------------------------------------
__global__ void __launch_bounds__(256) e2_kernel(const float* __restrict__ emb) {
    int tid = threadIdx.x;
    int tx = tid & 31, ty = tid >> 5;
    int j = blockIdx.x * 8 + ty;
    float s = 0.0f;
#pragma unroll
    for (int i = 0; i < 8; i++) {
        float v = emb[(size_t)j * CDIM + tx + 32 * i];
        s += v * v;
    }
#pragma unroll
    for (int m = 16; m; m >>= 1) s += __shfl_xor_sync(0xffffffffu, s, m);
    if (tx == 0) g_e2[j] = s;
}

// ---------------------------------------------------------------------------
// K3: tf32 mma.sync GEMM + approx argmin/argmax epilogue + candidate capture
// ---------------------------------------------------------------------------
#define SM_ROWKEY 0             // 128 u64
#define SM_COLKEY 1024          // 256 u64
#define SM_SS     3072          // 128 f
#define SM_E2S    3584          // 256 f
#define SM_DATA   4608
#define STAGE_A   (BM * ROWB)
#define STAGE_B   (BN * ROWB)
#define STAGE_SZ  (STAGE_A + STAGE_B)
#define NSTAGE 3
#define GEMM_SMEM (SM_DATA + NSTAGE * STAGE_SZ)

__device__ __forceinline__ void cpa16(uint32_t dst, const void* src) {
    asm volatile("cp.async.cg.shared.global [%0], [%1], 16;"
                 :: "r"(dst), "l"(src));
}

#define MMA8(d, a, b)                                                        \
    asm volatile(                                                            \
        "mma.sync.aligned.m16n8k8.row.col.f32.tf32.tf32.f32 "                \
        "{%0,%1,%2,%3},{%4,%5,%6,%7},{%8,%9},{%0,%1,%2,%3};"                 \
        : "+f"(d[0]), "+f"(d[1]), "+f"(d[2]), "+f"(d[3])                     \
        : "r"(a[0]), "r"(a[1]), "r"(a[2]), "r"(a[3]), "r"(b[0]), "r"(b[1]))

extern __shared__ char dynsmem[];

__global__ void __launch_bounds__(256, 1)
gemm_mma_kernel(const float* __restrict__ emb) {
    const int tid  = threadIdx.x;
    const int lane = tid & 31;
    const int warp = tid >> 5;
    const int gid  = lane >> 2;
    const int tig  = lane & 3;
    const int wm   = warp >> 2;
    const int wn   = warp & 3;
    const int m0   = blockIdx.y * BM;
    const int j0   = blockIdx.x * BN;

    unsigned long long* rowkey = (unsigned long long*)(dynsmem + SM_ROWKEY);
    unsigned long long* colkey = (unsigned long long*)(dynsmem + SM_COLKEY);
    float* Ss  = (float*)(dynsmem + SM_SS);
    float* e2s = (float*)(dynsmem + SM_E2S);

    uint32_t smbase;
    asm("{ .reg .u64 t; cvta.to.shared.u64 t, %1; cvt.u32.u64 %0, t; }"
        : "=r"(smbase) : "l"(dynsmem));

    const int t8 = tid >> 3;
    const int c8 = tid & 7;
    const float* gA0 = g_zf + (size_t)(m0 + t8) * CDIM + c8 * 4;
    const float* gB0 = emb  + (size_t)(j0 + t8) * CDIM + c8 * 4;
    const uint32_t dA0 = smbase + SM_DATA + t8 * ROWB + c8 * 16;
    const uint32_t dB0 = dA0 + STAGE_A;

    auto load_kb = [&](int s, int kb) {
        uint32_t so = s * STAGE_SZ;
        const float* ga = gA0 + kb * BK;
        const float* gb = gB0 + kb * BK;
#pragma unroll
        for (int i = 0; i < 4; i++)
            cpa16(dA0 + so + i * 32 * ROWB, ga + (size_t)i * 32 * CDIM);
#pragma unroll
        for (int i = 0; i < 8; i++)
            cpa16(dB0 + so + i * 32 * ROWB, gb + (size_t)i * 32 * CDIM);
    };

    if (tid < 128) { rowkey[tid] = ~0ull; Ss[tid] = g_S[m0 + tid]; }
    colkey[tid] = ~0ull;
    e2s[tid] = g_e2[j0 + tid];

    load_kb(0, 0);
    asm volatile("cp.async.commit_group;" ::: "memory");
    load_kb(1, 1);
    asm volatile("cp.async.commit_group;" ::: "memory");

    float acc[8][4][4];
#pragma unroll
    for (int nt = 0; nt < 8; nt++)
#pragma unroll
        for (int mt = 0; mt < 4; mt++)
#pragma unroll
            for (int c = 0; c < 4; c++) acc[nt][mt][c] = 0.0f;

    const int aBase = (wm * 64 + gid) * LDK + tig;
    const int bBase = (wn * 64 + gid) * LDK + tig;

#pragma unroll 1
    for (int kb = 0; kb < 8; kb++) {
        if (kb + 2 < 8) load_kb((kb + 2) % NSTAGE, kb + 2);
        asm volatile("cp.async.commit_group;" ::: "memory");
        asm volatile("cp.async.wait_group 2;" ::: "memory");
        __syncthreads();

        const uint32_t* Af =
            (const uint32_t*)(dynsmem + SM_DATA + (kb % NSTAGE) * STAGE_SZ);
        const uint32_t* Bf = Af + STAGE_A / 4;

#pragma unroll
        for (int ks = 0; ks < 4; ks++) {
            const int k = ks * 8;
            uint32_t a[4][4], b[8][2];
#pragma unroll
            for (int mt = 0; mt < 4; mt++) {
                int o = aBase + mt * 16 * LDK + k;
                a[mt][0] = Af[o];
                a[mt][1] = Af[o + 8 * LDK];
                a[mt][2] = Af[o + 4];
                a[mt][3] = Af[o + 8 * LDK + 4];
            }
#pragma unroll
            for (int nt = 0; nt < 8; nt++) {
                int o = bBase + nt * 8 * LDK + k;
                b[nt][0] = Bf[o];
                b[nt][1] = Bf[o + 4];
            }
#pragma unroll
            for (int nt = 0; nt < 8; nt++)
#pragma unroll
                for (int mt = 0; mt < 4; mt++)
                    MMA8(acc[nt][mt], a[mt], b[nt]);
        }
        __syncthreads();
    }

    // ---- epilogue pass 1: approx argmin (row) + argmax (col) ----
    float S_lo[4], S_hi[4];
#pragma unroll
    for (int mt = 0; mt < 4; mt++) {
        S_lo[mt] = Ss[wm * 64 + mt * 16 + gid];
        S_hi[mt] = Ss[wm * 64 + mt * 16 + gid + 8];
    }
    float bd_lo[4], bd_hi[4];
    int   bj_lo[4], bj_hi[4];
#pragma unroll
    for (int mt = 0; mt < 4; mt++) {
        bd_lo[mt] = __int_as_float(0x7f800000); bj_lo[mt] = 0;
        bd_hi[mt] = __int_as_float(0x7f800000); bj_hi[mt] = 0;
    }

#pragma unroll
    for (int nt = 0; nt < 8; nt++) {
        const int ca = wn * 64 + nt * 8 + 2 * tig;
        const float e2a = e2s[ca], e2b = e2s[ca + 1];
        const int ja = j0 + ca;
        unsigned long long cka = ~0ull, ckb = ~0ull;
#pragma unroll
        for (int mt = 0; mt < 4; mt++) {
            const unsigned rlo = (unsigned)(m0 + wm * 64 + mt * 16 + gid);
            const unsigned rhi = rlo + 8;
            float d00 = fmaf(-2.0f, acc[nt][mt][0], S_lo[mt] + e2a);
            float d01 = fmaf(-2.0f, acc[nt][mt][1], S_lo[mt] + e2b);
            float d10 = fmaf(-2.0f, acc[nt][mt][2], S_hi[mt] + e2a);
            float d11 = fmaf(-2.0f, acc[nt][mt][3], S_hi[mt] + e2b);
            if (d00 < bd_lo[mt]) { bd_lo[mt] = d00; bj_lo[mt] = ja; }
            if (d01 < bd_lo[mt]) { bd_lo[mt] = d01; bj_lo[mt] = ja + 1; }
            if (d10 < bd_hi[mt]) { bd_hi[mt] = d10; bj_hi[mt] = ja; }
            if (d11 < bd_hi[mt]) { bd_hi[mt] = d11; bj_hi[mt] = ja + 1; }
            unsigned long long k00 = (((unsigned long long)(~ford(d00))) << 32) | rlo;
            unsigned long long k10 = (((unsigned long long)(~ford(d10))) << 32) | rhi;
            unsigned long long k01 = (((unsigned long long)(~ford(d01))) << 32) | rlo;
            unsigned long long k11 = (((unsigned long long)(~ford(d11))) << 32) | rhi;
            cka = min(cka, min(k00, k10));
            ckb = min(ckb, min(k01, k11));
        }
#pragma unroll
        for (int off = 4; off < 32; off <<= 1) {
            cka = min(cka, __shfl_xor_sync(0xffffffffu, cka, off));
            ckb = min(ckb, __shfl_xor_sync(0xffffffffu, ckb, off));
        }
        if (gid == 0) {
            atomicMin(&colkey[ca], cka);
            atomicMin(&colkey[ca + 1], ckb);
        }
    }
#pragma unroll
    for (int mt = 0; mt < 4; mt++) {
        unsigned long long klo =
            (((unsigned long long)ford(bd_lo[mt])) << 32) | (unsigned)bj_lo[mt];
        unsigned long long khi =
            (((unsigned long long)ford(bd_hi[mt])) << 32) | (unsigned)bj_hi[mt];
#pragma unroll
        for (int off = 1; off < 4; off <<= 1) {
            klo = min(klo, __shfl_xor_sync(0xffffffffu, klo, off));
            khi = min(khi, __shfl_xor_sync(0xffffffffu, khi, off));
        }
        if (tig == 0) {
            atomicMin(&rowkey[wm * 64 + mt * 16 + gid], klo);
            atomicMin(&rowkey[wm * 64 + mt * 16 + gid + 8], khi);
        }
    }
    __syncthreads();

    // export block minima and column maxima
    if (tid < 128) g_blockmin[m0 + tid][blockIdx.x] = rowkey[tid];
    atomicMin(&g_maxkey[j0 + tid], colkey[tid]);

    // ---- epilogue pass 2: append near-tie candidates (d within EPSB of
    // CTA-local row min, excluding the winner itself) ----
#pragma unroll
    for (int mt = 0; mt < 4; mt++) {
        const int rl = wm * 64 + mt * 16 + gid;
        const int rh = rl + 8;
        const unsigned long long rkl = rowkey[rl];
        const unsigned long long rkh = rowkey[rh];
        const float vl = unford((unsigned)(rkl >> 32)) + EPSB;
        const float vh = unford((unsigned)(rkh >> 32)) + EPSB;
#pragma unroll
        for (int nt = 0; nt < 8; nt++) {
            const int ca = wn * 64 + nt * 8 + 2 * tig;
            const float e2a = e2s[ca], e2b = e2s[ca + 1];
            const unsigned ja = (unsigned)(j0 + ca);
            float d00 = fmaf(-2.0f, acc[nt][mt][0], S_lo[mt] + e2a);
            float d01 = fmaf(-2.0f, acc[nt][mt][1], S_lo[mt] + e2b);
            float d10 = fmaf(-2.0f, acc[nt][mt][2], S_hi[mt] + e2a);
            float d11 = fmaf(-2.0f, acc[nt][mt][3], S_hi[mt] + e2b);
            if (d00 < vl) {
                unsigned long long k = (((unsigned long long)ford(d00)) << 32) | ja;
                if (k != rkl) {
                    unsigned slot = atomicAdd(&g_xcnt, 1u);
                    if (slot < MAXX)
                        g_extras[slot] = ((unsigned)(m0 + rl) << 13) | ja;
                }
            }
            if (d01 < vl) {
                unsigned long long k = (((unsigned long long)ford(d01)) << 32) | (ja + 1);
                if (k != rkl) {
                    unsigned slot = atomicAdd(&g_xcnt, 1u);
                    if (slot < MAXX)
                        g_extras[slot] = ((unsigned)(m0 + rl) << 13) | (ja + 1);
                }
            }
            if (d10 < vh) {
                unsigned long long k = (((unsigned long long)ford(d10)) << 32) | ja;
                if (k != rkh) {
                    unsigned slot = atomicAdd(&g_xcnt, 1u);
                    if (slot < MAXX)
                        g_extras[slot] = ((unsigned)(m0 + rh) << 13) | ja;
                }
            }
            if (d11 < vh) {
                unsigned long long k = (((unsigned long long)ford(d11)) << 32) | (ja + 1);
                if (k != rkh) {
                    unsigned slot = atomicAdd(&g_xcnt, 1u);
                    if (slot < MAXX)
                        g_extras[slot] = ((unsigned)(m0 + rh) << 13) | (ja + 1);
                }
            }
        }
    }
}

// ---------------------------------------------------------------------------
// K4a: exact recompute of appended extras (double dot, fp32-grid distance)
// ---------------------------------------------------------------------------
__global__ void __launch_bounds__(256) extras_kernel(const float* __restrict__ emb) {
    const unsigned cnt = min(g_xcnt, (unsigned)MAXX);
    const int lane = threadIdx.x & 31;
    const int wid = (blockIdx.x * blockDim.x + threadIdx.x) >> 5;
    const int nw = (gridDim.x * blockDim.x) >> 5;
    for (unsigned i = wid; i < cnt; i += nw) {
        unsigned e = g_extras[i];
        int n = e >> 13;
        int j = e & 8191;
        float d32 = exact_d32(emb, n, j, lane);
        unsigned long long key =
            (((unsigned long long)ford(d32)) << 32) | (unsigned)j;
        if (lane == 0) atomicMin(&g_exkey[n], key);
    }
}

// ---------------------------------------------------------------------------
// K4b: per-row token resolution (+ histogram)
// ---------------------------------------------------------------------------
__global__ void __launch_bounds__(256) tokenfix_kernel(const float* __restrict__ emb) {
    const int lane = threadIdx.x & 31;
    const int wid = (blockIdx.x * blockDim.x + threadIdx.x) >> 5;
    const int nw = (gridDim.x * blockDim.x) >> 5;
    for (int n = wid; n < NFEAT; n += nw) {
        unsigned long long k = g_blockmin[n][lane];   // NJB == 32 == warp size
        unsigned long long gm = k;
#pragma unroll
        for (int m = 16; m; m >>= 1)
            gm = min(gm, __shfl_xor_sync(0xffffffffu, gm, m));
        float thresh = unford((unsigned)(gm >> 32)) + EPSB;
        bool cand = unford((unsigned)(k >> 32)) < thresh;
        unsigned bal = __ballot_sync(0xffffffffu, cand);
        unsigned long long ex = g_exkey[n];
        unsigned tok;
        if (__popc(bal) == 1 && ex == ~0ull) {
            tok = (unsigned)(gm & 0xffffffffull);
        } else {
            unsigned long long best = ex;
            unsigned b = bal;
            while (b) {
                int src = __ffs(b) - 1;
                b &= b - 1;
                unsigned jj = __shfl_sync(0xffffffffu,
                                          (unsigned)(k & 0xffffffffull), src);
                float d32 = exact_d32(emb, n, (int)jj, lane);
                unsigned long long key =
                    (((unsigned long long)ford(d32)) << 32) | jj;
                best = min(best, key);
            }
            tok = (unsigned)(best & 0xffffffffull);
        }
        if (lane == 0) {
            g_token[n] = (int)tok;
            atomicAdd(&g_hist[tok], 1u);
        }
    }
}

// ---------------------------------------------------------------------------
// K4c: far indices from approx argmax keys
// ---------------------------------------------------------------------------
__global__ void far_kernel() {
    int j = blockIdx.x * blockDim.x + threadIdx.x;
    if (j < KCODE) g_far[j] = (int)(g_maxkey[j] & 0xffffffffull);
}

// ---------------------------------------------------------------------------
// K5: z_q straight-through output (transposed back) + SSE reduction
// ---------------------------------------------------------------------------
__global__ void __launch_bounds__(256) zq_kernel(const float* __restrict__ emb,
                                                 float* __restrict__ out) {
    __shared__ float rowbuf[32][CDIM + 1];
    __shared__ int stok[32];
    __shared__ float red[8];
    int tid = threadIdx.x;
    int b = blockIdx.x >> 5, h = blockIdx.x & 31;
    int nbase = b * 1024 + h * 32;
    if (tid < 32) stok[tid] = g_token[nbase + tid];
    __syncthreads();
    float acc = 0.0f;
#pragma unroll 4
    for (int w = 0; w < 32; w++) {
        float v  = emb[(size_t)stok[w] * CDIM + tid];
        float zv = g_zf[(size_t)(nbase + w) * CDIM + tid];
        float diff = __fsub_rn(v, zv);
        acc = fmaf(diff, diff, acc);
        rowbuf[w][tid] = __fadd_rn(zv, diff);
    }
    float s = acc;
#pragma unroll
    for (int m = 16; m; m >>= 1) s += __shfl_xor_sync(0xffffffffu, s, m);
    if ((tid & 31) == 0) red[tid >> 5] = s;
    __syncthreads();
    if (tid == 0) {
        float t = 0.0f;
#pragma unroll
        for (int i = 0; i < 8; i++) t += red[i];
        atomicAdd(&g_sse, t);
    }
    int tx = tid & 31, ty = tid >> 5;
#pragma unroll
    for (int i = 0; i < 32; i++) {
        int c = i * 8 + ty;
        out[OUT_ZQ + (((size_t)b * CDIM + c) * HDIM + h) * WDIM + tx] = rowbuf[tx][c];
    }
}

// ---------------------------------------------------------------------------
// K6: per-code update
// ---------------------------------------------------------------------------
__global__ void __launch_bounds__(256) code_kernel(const float* __restrict__ emb,
                                                   const float* __restrict__ eprob,
                                                   float* __restrict__ out) {
    int j = blockIdx.x;
    int c = threadIdx.x;
    unsigned hcnt = g_hist[j];
    float avg = (float)hcnt * (1.0f / 16384.0f);
    float np  = __fadd_rn(__fmul_rn(eprob[j], 0.99f), __fmul_rn(avg, 0.01f));
    float t = __fmul_rn(np, 8192.0f);
    t = __fmul_rn(t, 10.0f);
    t = __fdiv_rn(t, 0.01f);
    float decay = expf(-t - 0.001f);
    float omd = __fsub_rn(1.0f, decay);
    if (c == 0) {
        out[OUT_NPROB + j] = np;
        atomicAdd(&g_ent, avg * logf(avg + 1e-10f));
        if (hcnt > 0) atomicAdd(&g_util, 1u);
    }
    int fi = g_far[j];
    float rf = g_zf[(size_t)fi * CDIM + c];
    float e  = emb[(size_t)j * CDIM + c];
    out[OUT_NEMB + (size_t)j * CDIM + c] =
        __fadd_rn(__fmul_rn(e, omd), __fmul_rn(rf, decay));
}

// ---------------------------------------------------------------------------
// K7: finalize scalars
// ---------------------------------------------------------------------------
__global__ void fin_kernel(float* __restrict__ out) {
    float sse = g_sse;
    float mse = sse / 4194304.0f;
    out[OUT_LOSS] = __fadd_rn(__fmul_rn(0.25f, mse), mse);
    out[OUT_QERR] = sse / 16384.0f;
    out[OUT_UTIL] = (float)g_util / 8192.0f;
    out[OUT_PERP] = expf(-g_ent);
}

// ---------------------------------------------------------------------------
extern "C" void kernel_launch(void* const* d_in, const int* in_sizes, int n_in,
                              void* d_out, int out_size) {
    (void)in_sizes; (void)n_in; (void)out_size;
    const float* z     = (const float*)d_in[0];
    const float* emb   = (const float*)d_in[1];
    const float* eprob = (const float*)d_in[2];
    float* out = (float*)d_out;

    static int smem_set = 0;
    if (!smem_set) {
        cudaFuncSetAttribute(gemm_mma_kernel,
                             cudaFuncAttributeMaxDynamicSharedMemorySize,
                             GEMM_SMEM);
        smem_set = 1;
    }

    init_kernel<<<64, 256>>>();
    prep_kernel<<<BATCH * HDIM, 256>>>(z);
    e2_kernel<<<KCODE / 8, 256>>>(emb);
    gemm_mma_kernel<<<dim3(NJB, NFEAT / BM), 256, GEMM_SMEM>>>(emb);
    extras_kernel<<<256, 256>>>(emb);
    tokenfix_kernel<<<256, 256>>>(emb);
    far_kernel<<<KCODE / 256, 256>>>();
    zq_kernel<<<BATCH * HDIM, 256>>>(emb, out);
    code_kernel<<<KCODE, 256>>>(emb, eprob, out);
    fin_kernel<<<1, 1>>>(out);
}

// round 5
// speedup vs baseline: 2.1016x; 1.0565x over previous
#include <cuda_runtime.h>
#include <math.h>
#include <stdint.h>

// Problem constants
#define NFEAT 16384          // B*H*W = 16*32*32
#define KCODE 8192           // codebook size
#define CDIM  256            // codebook dim
#define BATCH 16
#define HDIM  32
#define WDIM  32

// Output layout (float32, concatenated in reference tuple order)
#define OUT_ZQ    0
#define OUT_LOSS  4194304
#define OUT_QERR  4194305
#define OUT_UTIL  4194306
#define OUT_PERP  4194307
#define OUT_NEMB  4194308
#define OUT_NPROB 6291460

// GEMM tiling
#define BM 128
#define BN 256
#define NJB (KCODE / BN)     // 32 j-blocks
#define BK 32
#define LDK 40               // padded row (floats) -> conflict-free LDS.64
#define ROWB (LDK * 4)       // 160 bytes

// candidate window: must exceed 2*ulp(256) + 2*tf32_err  (~4.1e-5)
#define EPSB 8e-5f
#define MAXX (1 << 21)

// Scratch (device globals; no dynamic allocation allowed)
__device__ float              g_zf[NFEAT * CDIM];
__device__ float              g_S[NFEAT];
__device__ float              g_e2[KCODE];
__device__ unsigned long long g_blockmin[NFEAT][NJB];
__device__ unsigned long long g_exkey[NFEAT];
__device__ unsigned int       g_extras[MAXX];
__device__ unsigned int       g_xcnt;
__device__ unsigned long long g_maxkey[KCODE];
__device__ unsigned int       g_hist[KCODE];
__device__ int                g_token[NFEAT];
__device__ float              g_sse;
__device__ float              g_ent;
__device__ unsigned int       g_util;

__device__ __forceinline__ unsigned int ford(float f) {
    unsigned int u = __float_as_uint(f);
    return u ^ ((((int)u) >> 31) | 0x80000000u);
}
__device__ __forceinline__ float unford(unsigned int u) {
    unsigned int v = (u & 0x80000000u) ? (u ^ 0x80000000u) : ~u;
    return __uint_as_float(v);
}

// exact distance on reference fp32 grid (double dot). Warp-cooperative.
__device__ __forceinline__ float exact_d32(const float* __restrict__ emb,
                                           int n, int j, int lane) {
    const float* zr = g_zf + (size_t)n * CDIM;
    const float* er = emb + (size_t)j * CDIM;
    double dd = 0.0;
#pragma unroll
    for (int c = 0; c < CDIM / 32; c++)
        dd += (double)zr[lane + 32 * c] * (double)er[lane + 32 * c];
#pragma unroll
    for (int m = 16; m; m >>= 1) dd += __shfl_xor_sync(0xffffffffu, dd, m);
    float dotf = (float)dd;
    return __fsub_rn(__fadd_rn(g_S[n], g_e2[j]), 2.0f * dotf);
}

// ---------------------------------------------------------------------------
// K0: init scratch
// ---------------------------------------------------------------------------
__global__ void init_kernel() {
    int i = blockIdx.x * blockDim.x + threadIdx.x;
    if (i < NFEAT) g_exkey[i] = ~0ull;
    if (i < KCODE) { g_maxkey[i] = ~0ull; g_hist[i] = 0u; }
    if (i == 0) { g_sse = 0.0f; g_ent = 0.0f; g_util = 0u; g_xcnt = 0u; }
}

// ---------------------------------------------------------------------------
// K1: transpose z -> zf, compute S
// ---------------------------------------------------------------------------
__global__ void __launch_bounds__(256) prep_kernel(const float* __restrict__ z) {
    __shared__ float tile[32][CDIM + 1];
    int tid = threadIdx.x;
    int tx = tid & 31, ty = tid >> 5;
    int b = blockIdx.x >> 5, h = blockIdx.x & 31;
    const float* zp = z + (size_t)b * (CDIM * HDIM * WDIM) + h * WDIM;
#pragma unroll
    for (int i = 0; i < 32; i++) {
        int c = i * 8 + ty;
        tile[tx][c] = zp[c * (HDIM * WDIM) + tx];
    }
    __syncthreads();
    int nbase = b * 1024 + h * 32;
#pragma unroll
    for (int j = 0; j < 4; j++) {
        int w = ty * 4 + j;
        int n = nbase + w;
        float s = 0.0f;
#pragma unroll
        for (int i = 0; i < 8; i++) {
            int c = tx + 32 * i;
            float v = tile[w][c];
            g_zf[(size_t)n * CDIM + c] = v;
            s += v * v;
        }
#pragma unroll
        for (int m = 16; m; m >>= 1) s += __shfl_xor_sync(0xffffffffu, s, m);
        if (tx == 0) g_S[n] = s;
    }
}

// ---------------------------------------------------------------------------
// K2: e2
// ---------------------------------------------------------------------------
__global__ void __launch_bounds__(256) e2_kernel(const float* __restrict__ emb) {
    int tid = threadIdx.x;
    int tx = tid & 31, ty = tid >> 5;
    int j = blockIdx.x * 8 + ty;
    float s = 0.0f;
#pragma unroll
    for (int i = 0; i < 8; i++) {
        float v = emb[(size_t)j * CDIM + tx + 32 * i];
        s += v * v;
    }
#pragma unroll
    for (int m = 16; m; m >>= 1) s += __shfl_xor_sync(0xffffffffu, s, m);
    if (tx == 0) g_e2[j] = s;
}

// ---------------------------------------------------------------------------
// K3: tf32 mma GEMM (512 threads, 16 warps 2Mx8N, warp tile 64x32)
// k-slot re-pairing: slots (tig, tig+4) fed with phys cols (2tig, 2tig+1)
// for BOTH A and B -> identical dot, fragments load as LDS.64.
// ---------------------------------------------------------------------------
#define SM_ROWKEY 0             // 128 u64
#define SM_COLKEY 1024          // 256 u64
#define SM_SS     3072          // 128 f
#define SM_E2S    3584          // 256 f
#define SM_DATA   4608
#define STAGE_A   (BM * ROWB)               // 20480
#define STAGE_B   (BN * ROWB)               // 40960
#define STAGE_SZ  (STAGE_A + STAGE_B)       // 61440
#define NSTAGE 3
#define GEMM_SMEM (SM_DATA + NSTAGE * STAGE_SZ)   // 188928

__device__ __forceinline__ void cpa16(uint32_t dst, const void* src) {
    asm volatile("cp.async.cg.shared.global [%0], [%1], 16;"
                 :: "r"(dst), "l"(src));
}

#define MMA8(d, a0, a1, a2, a3, b0, b1)                                      \
    asm volatile(                                                            \
        "mma.sync.aligned.m16n8k8.row.col.f32.tf32.tf32.f32 "                \
        "{%0,%1,%2,%3},{%4,%5,%6,%7},{%8,%9},{%0,%1,%2,%3};"                 \
        : "+f"(d[0]), "+f"(d[1]), "+f"(d[2]), "+f"(d[3])                     \
        : "r"(a0), "r"(a1), "r"(a2), "r"(a3), "r"(b0), "r"(b1))

extern __shared__ char dynsmem[];

__global__ void __launch_bounds__(512, 1)
gemm_mma_kernel(const float* __restrict__ emb) {
    const int tid  = threadIdx.x;
    const int lane = tid & 31;
    const int warp = tid >> 5;
    const int gid  = lane >> 2;     // 0..7
    const int tig  = lane & 3;      // 0..3
    const int wm   = warp >> 3;     // 0..1  (M split: 64 rows each)
    const int wn   = warp & 7;      // 0..7  (N split: 32 cols each)
    const int m0   = blockIdx.y * BM;
    const int j0   = blockIdx.x * BN;

    unsigned long long* rowkey = (unsigned long long*)(dynsmem + SM_ROWKEY);
    unsigned long long* colkey = (unsigned long long*)(dynsmem + SM_COLKEY);
    float* Ss  = (float*)(dynsmem + SM_SS);
    float* e2s = (float*)(dynsmem + SM_E2S);

    uint32_t smbase;
    asm("{ .reg .u64 t; cvta.to.shared.u64 t, %1; cvt.u32.u64 %0, t; }"
        : "=r"(smbase) : "l"(dynsmem));

    // staging: 512 threads, t8 = row (0..63), c8 = 16B seg (0..7)
    const int t8 = tid >> 3;
    const int c8 = tid & 7;
    const float* gA0 = g_zf + (size_t)(m0 + t8) * CDIM + c8 * 4;
    const float* gB0 = emb  + (size_t)(j0 + t8) * CDIM + c8 * 4;
    const uint32_t dA0 = smbase + SM_DATA + t8 * ROWB + c8 * 16;
    const uint32_t dB0 = dA0 + STAGE_A;

    auto load_kb = [&](int s, int kb) {
        uint32_t so = s * STAGE_SZ;
        const float* ga = gA0 + kb * BK;
        const float* gb = gB0 + kb * BK;
#pragma unroll
        for (int i = 0; i < 2; i++)
            cpa16(dA0 + so + i * 64 * ROWB, ga + (size_t)i * 64 * CDIM);
#pragma unroll
        for (int i = 0; i < 4; i++)
            cpa16(dB0 + so + i * 64 * ROWB, gb + (size_t)i * 64 * CDIM);
    };

    if (tid < 128) { rowkey[tid] = ~0ull; Ss[tid] = g_S[m0 + tid]; }
    if (tid < 256) { colkey[tid] = ~0ull; e2s[tid] = g_e2[j0 + tid]; }

    load_kb(0, 0);
    asm volatile("cp.async.commit_group;" ::: "memory");
    load_kb(1, 1);
    asm volatile("cp.async.commit_group;" ::: "memory");

    float acc[4][4][4];
#pragma unroll
    for (int nt = 0; nt < 4; nt++)
#pragma unroll
        for (int mt = 0; mt < 4; mt++)
#pragma unroll
            for (int c = 0; c < 4; c++) acc[nt][mt][c] = 0.0f;

    // fragment bases in uint2 (8B) units: (row*LDK + 2*tig)/2 = row*20 + tig
    const int aBase2 = (wm * 64 + gid) * (LDK / 2) + tig;
    const int bBase2 = (wn * 32 + gid) * (LDK / 2) + tig;

#pragma unroll 1
    for (int kb = 0; kb < 8; kb++) {
        if (kb + 2 < 8) load_kb((kb + 2) % NSTAGE, kb + 2);
        asm volatile("cp.async.commit_group;" ::: "memory");
        asm volatile("cp.async.wait_group 2;" ::: "memory");
        __syncthreads();

        const uint2* Af2 =
            (const uint2*)(dynsmem + SM_DATA + (kb % NSTAGE) * STAGE_SZ);
        const uint2* Bf2 = Af2 + STAGE_A / 8;

#pragma unroll
        for (int ks = 0; ks < 4; ks++) {
            const int ko = ks * 4;              // k step in uint2 units
            uint2 alo[4], ahi[4], bv[4];
#pragma unroll
            for (int mt = 0; mt < 4; mt++) {
                int o = aBase2 + mt * 16 * (LDK / 2) + ko;
                alo[mt] = Af2[o];
                ahi[mt] = Af2[o + 8 * (LDK / 2)];
            }
#pragma unroll
            for (int nt = 0; nt < 4; nt++)
                bv[nt] = Bf2[bBase2 + nt * 8 * (LDK / 2) + ko];
#pragma unroll
            for (int nt = 0; nt < 4; nt++)
#pragma unroll
                for (int mt = 0; mt < 4; mt++)
                    MMA8(acc[nt][mt], alo[mt].x, ahi[mt].x,
                         alo[mt].y, ahi[mt].y, bv[nt].x, bv[nt].y);
        }
        __syncthreads();
    }

    // ---- epilogue pass 1: approx argmin (row) + argmax (col) ----
    float S_lo[4], S_hi[4];
#pragma unroll
    for (int mt = 0; mt < 4; mt++) {
        S_lo[mt] = Ss[wm * 64 + mt * 16 + gid];
        S_hi[mt] = Ss[wm * 64 + mt * 16 + gid + 8];
    }
    float bd_lo[4], bd_hi[4];
    int   bj_lo[4], bj_hi[4];
#pragma unroll
    for (int mt = 0; mt < 4; mt++) {
        bd_lo[mt] = __int_as_float(0x7f800000); bj_lo[mt] = 0;
        bd_hi[mt] = __int_as_float(0x7f800000); bj_hi[mt] = 0;
    }

#pragma unroll
    for (int nt = 0; nt < 4; nt++) {
        const int ca = wn * 32 + nt * 8 + 2 * tig;
        const float e2a = e2s[ca], e2b = e2s[ca + 1];
        const int ja = j0 + ca;
        unsigned long long cka = ~0ull, ckb = ~0ull;
#pragma unroll
        for (int mt = 0; mt < 4; mt++) {
            const unsigned rlo = (unsigned)(m0 + wm * 64 + mt * 16 + gid);
            const unsigned rhi = rlo + 8;
            float d00 = fmaf(-2.0f, acc[nt][mt][0], S_lo[mt] + e2a);
            float d01 = fmaf(-2.0f, acc[nt][mt][1], S_lo[mt] + e2b);
            float d10 = fmaf(-2.0f, acc[nt][mt][2], S_hi[mt] + e2a);
            float d11 = fmaf(-2.0f, acc[nt][mt][3], S_hi[mt] + e2b);
            if (d00 < bd_lo[mt]) { bd_lo[mt] = d00; bj_lo[mt] = ja; }
            if (d01 < bd_lo[mt]) { bd_lo[mt] = d01; bj_lo[mt] = ja + 1; }
            if (d10 < bd_hi[mt]) { bd_hi[mt] = d10; bj_hi[mt] = ja; }
            if (d11 < bd_hi[mt]) { bd_hi[mt] = d11; bj_hi[mt] = ja + 1; }
            unsigned long long k00 = (((unsigned long long)(~ford(d00))) << 32) | rlo;
            unsigned long long k10 = (((unsigned long long)(~ford(d10))) << 32) | rhi;
            unsigned long long k01 = (((unsigned long long)(~ford(d01))) << 32) | rlo;
            unsigned long long k11 = (((unsigned long long)(~ford(d11))) << 32) | rhi;
            cka = min(cka, min(k00, k10));
            ckb = min(ckb, min(k01, k11));
        }
#pragma unroll
        for (int off = 4; off < 32; off <<= 1) {
            cka = min(cka, __shfl_xor_sync(0xffffffffu, cka, off));
            ckb = min(ckb, __shfl_xor_sync(0xffffffffu, ckb, off));
        }
        if (gid == 0) {
            atomicMin(&colkey[ca], cka);
            atomicMin(&colkey[ca + 1], ckb);
        }
    }
#pragma unroll
    for (int mt = 0; mt < 4; mt++) {
        unsigned long long klo =
            (((unsigned long long)ford(bd_lo[mt])) << 32) | (unsigned)bj_lo[mt];
        unsigned long long khi =
            (((unsigned long long)ford(bd_hi[mt])) << 32) | (unsigned)bj_hi[mt];
#pragma unroll
        for (int off = 1; off < 4; off <<= 1) {
            klo = min(klo, __shfl_xor_sync(0xffffffffu, klo, off));
            khi = min(khi, __shfl_xor_sync(0xffffffffu, khi, off));
        }
        if (tig == 0) {
            atomicMin(&rowkey[wm * 64 + mt * 16 + gid], klo);
            atomicMin(&rowkey[wm * 64 + mt * 16 + gid + 8], khi);
        }
    }
    __syncthreads();

    if (tid < 128) g_blockmin[m0 + tid][blockIdx.x] = rowkey[tid];
    if (tid < 256) atomicMin(&g_maxkey[j0 + tid], colkey[tid]);

    // ---- epilogue pass 2: append near-tie candidates ----
#pragma unroll
    for (int mt = 0; mt < 4; mt++) {
        const int rl = wm * 64 + mt * 16 + gid;
        const int rh = rl + 8;
        const unsigned long long rkl = rowkey[rl];
        const unsigned long long rkh = rowkey[rh];
        const float vl = unford((unsigned)(rkl >> 32)) + EPSB;
        const float vh = unford((unsigned)(rkh >> 32)) + EPSB;
#pragma unroll
        for (int nt = 0; nt < 4; nt++) {
            const int ca = wn * 32 + nt * 8 + 2 * tig;
            const float e2a = e2s[ca], e2b = e2s[ca + 1];
            const unsigned ja = (unsigned)(j0 + ca);
            float d00 = fmaf(-2.0f, acc[nt][mt][0], S_lo[mt] + e2a);
            float d01 = fmaf(-2.0f, acc[nt][mt][1], S_lo[mt] + e2b);
            float d10 = fmaf(-2.0f, acc[nt][mt][2], S_hi[mt] + e2a);
            float d11 = fmaf(-2.0f, acc[nt][mt][3], S_hi[mt] + e2b);
            if (d00 < vl) {
                unsigned long long k = (((unsigned long long)ford(d00)) << 32) | ja;
                if (k != rkl) {
                    unsigned slot = atomicAdd(&g_xcnt, 1u);
                    if (slot < MAXX)
                        g_extras[slot] = ((unsigned)(m0 + rl) << 13) | ja;
                }
            }
            if (d01 < vl) {
                unsigned long long k = (((unsigned long long)ford(d01)) << 32) | (ja + 1);
                if (k != rkl) {
                    unsigned slot = atomicAdd(&g_xcnt, 1u);
                    if (slot < MAXX)
                        g_extras[slot] = ((unsigned)(m0 + rl) << 13) | (ja + 1);
                }
            }
            if (d10 < vh) {
                unsigned long long k = (((unsigned long long)ford(d10)) << 32) | ja;
                if (k != rkh) {
                    unsigned slot = atomicAdd(&g_xcnt, 1u);
                    if (slot < MAXX)
                        g_extras[slot] = ((unsigned)(m0 + rh) << 13) | ja;
                }
            }
            if (d11 < vh) {
                unsigned long long k = (((unsigned long long)ford(d11)) << 32) | (ja + 1);
                if (k != rkh) {
                    unsigned slot = atomicAdd(&g_xcnt, 1u);
                    if (slot < MAXX)
                        g_extras[slot] = ((unsigned)(m0 + rh) << 13) | (ja + 1);
                }
            }
        }
    }
}

// ---------------------------------------------------------------------------
// K4a: exact recompute of appended extras
// ---------------------------------------------------------------------------
__global__ void __launch_bounds__(256) extras_kernel(const float* __restrict__ emb) {
    const unsigned cnt = min(g_xcnt, (unsigned)MAXX);
    const int lane = threadIdx.x & 31;
    const int wid = (blockIdx.x * blockDim.x + threadIdx.x) >> 5;
    const int nw = (gridDim.x * blockDim.x) >> 5;
    for (unsigned i = wid; i < cnt; i += nw) {
        unsigned e = g_extras[i];
        int n = e >> 13;
        int j = e & 8191;
        float d32 = exact_d32(emb, n, j, lane);
        unsigned long long key =
            (((unsigned long long)ford(d32)) << 32) | (unsigned)j;
        if (lane == 0) atomicMin(&g_exkey[n], key);
    }
}

// ---------------------------------------------------------------------------
// K4b: per-row token resolution (+ histogram)
// ---------------------------------------------------------------------------
__global__ void __launch_bounds__(256) tokenfix_kernel(const float* __restrict__ emb) {
    const int lane = threadIdx.x & 31;
    const int wid = (blockIdx.x * blockDim.x + threadIdx.x) >> 5;
    const int nw = (gridDim.x * blockDim.x) >> 5;
    for (int n = wid; n < NFEAT; n += nw) {
        unsigned long long k = g_blockmin[n][lane];   // NJB == 32
        unsigned long long gm = k;
#pragma unroll
        for (int m = 16; m; m >>= 1)
            gm = min(gm, __shfl_xor_sync(0xffffffffu, gm, m));
        float thresh = unford((unsigned)(gm >> 32)) + EPSB;
        bool cand = unford((unsigned)(k >> 32)) < thresh;
        unsigned bal = __ballot_sync(0xffffffffu, cand);
        unsigned long long ex = g_exkey[n];
        unsigned tok;
        if (__popc(bal) == 1 && ex == ~0ull) {
            tok = (unsigned)(gm & 0xffffffffull);
        } else {
            unsigned long long best = ex;
            unsigned b = bal;
            while (b) {
                int src = __ffs(b) - 1;
                b &= b - 1;
                unsigned jj = __shfl_sync(0xffffffffu,
                                          (unsigned)(k & 0xffffffffull), src);
                float d32 = exact_d32(emb, n, (int)jj, lane);
                unsigned long long key =
                    (((unsigned long long)ford(d32)) << 32) | jj;
                best = min(best, key);
            }
            tok = (unsigned)(best & 0xffffffffull);
        }
        if (lane == 0) {
            g_token[n] = (int)tok;
            atomicAdd(&g_hist[tok], 1u);
        }
    }
}

// ---------------------------------------------------------------------------
// K5: z_q straight-through output + SSE
// ---------------------------------------------------------------------------
__global__ void __launch_bounds__(256) zq_kernel(const float* __restrict__ emb,
                                                 float* __restrict__ out) {
    __shared__ float rowbuf[32][CDIM + 1];
    __shared__ int stok[32];
    __shared__ float red[8];
    int tid = threadIdx.x;
    int b = blockIdx.x >> 5, h = blockIdx.x & 31;
    int nbase = b * 1024 + h * 32;
    if (tid < 32) stok[tid] = g_token[nbase + tid];
    __syncthreads();
    float acc = 0.0f;
#pragma unroll 4
    for (int w = 0; w < 32; w++) {
        float v  = emb[(size_t)stok[w] * CDIM + tid];
        float zv = g_zf[(size_t)(nbase + w) * CDIM + tid];
        float diff = __fsub_rn(v, zv);
        acc = fmaf(diff, diff, acc);
        rowbuf[w][tid] = __fadd_rn(zv, diff);
    }
    float s = acc;
#pragma unroll
    for (int m = 16; m; m >>= 1) s += __shfl_xor_sync(0xffffffffu, s, m);
    if ((tid & 31) == 0) red[tid >> 5] = s;
    __syncthreads();
    if (tid == 0) {
        float t = 0.0f;
#pragma unroll
        for (int i = 0; i < 8; i++) t += red[i];
        atomicAdd(&g_sse, t);
    }
    int tx = tid & 31, ty = tid >> 5;
#pragma unroll
    for (int i = 0; i < 32; i++) {
        int c = i * 8 + ty;
        out[OUT_ZQ + (((size_t)b * CDIM + c) * HDIM + h) * WDIM + tx] = rowbuf[tx][c];
    }
}

// ---------------------------------------------------------------------------
// K6: per-code update (far index read inline from g_maxkey)
// ---------------------------------------------------------------------------
__global__ void __launch_bounds__(256) code_kernel(const float* __restrict__ emb,
                                                   const float* __restrict__ eprob,
                                                   float* __restrict__ out) {
    int j = blockIdx.x;
    int c = threadIdx.x;
    unsigned hcnt = g_hist[j];
    float avg = (float)hcnt * (1.0f / 16384.0f);
    float np  = __fadd_rn(__fmul_rn(eprob[j], 0.99f), __fmul_rn(avg, 0.01f));
    float t = __fmul_rn(np, 8192.0f);
    t = __fmul_rn(t, 10.0f);
    t = __fdiv_rn(t, 0.01f);
    float decay = expf(-t - 0.001f);
    float omd = __fsub_rn(1.0f, decay);
    if (c == 0) {
        out[OUT_NPROB + j] = np;
        atomicAdd(&g_ent, avg * logf(avg + 1e-10f));
        if (hcnt > 0) atomicAdd(&g_util, 1u);
    }
    int fi = (int)(g_maxkey[j] & 0xffffffffull);
    float rf = g_zf[(size_t)fi * CDIM + c];
    float e  = emb[(size_t)j * CDIM + c];
    out[OUT_NEMB + (size_t)j * CDIM + c] =
        __fadd_rn(__fmul_rn(e, omd), __fmul_rn(rf, decay));
}

// ---------------------------------------------------------------------------
// K7: finalize scalars
// ---------------------------------------------------------------------------
__global__ void fin_kernel(float* __restrict__ out) {
    float sse = g_sse;
    float mse = sse / 4194304.0f;
    out[OUT_LOSS] = __fadd_rn(__fmul_rn(0.25f, mse), mse);
    out[OUT_QERR] = sse / 16384.0f;
    out[OUT_UTIL] = (float)g_util / 8192.0f;
    out[OUT_PERP] = expf(-g_ent);
}

// ---------------------------------------------------------------------------
extern "C" void kernel_launch(void* const* d_in, const int* in_sizes, int n_in,
                              void* d_out, int out_size) {
    (void)in_sizes; (void)n_in; (void)out_size;
    const float* z     = (const float*)d_in[0];
    const float* emb   = (const float*)d_in[1];
    const float* eprob = (const float*)d_in[2];
    float* out = (float*)d_out;

    static int smem_set = 0;
    if (!smem_set) {
        cudaFuncSetAttribute(gemm_mma_kernel,
                             cudaFuncAttributeMaxDynamicSharedMemorySize,
                             GEMM_SMEM);
        smem_set = 1;
    }

    init_kernel<<<64, 256>>>();
    prep_kernel<<<BATCH * HDIM, 256>>>(z);
    e2_kernel<<<KCODE / 8, 256>>>(emb);
    gemm_mma_kernel<<<dim3(NJB, NFEAT / BM), 512, GEMM_SMEM>>>(emb);
    extras_kernel<<<256, 256>>>(emb);
    tokenfix_kernel<<<256, 256>>>(emb);
    zq_kernel<<<BATCH * HDIM, 256>>>(emb, out);
    code_kernel<<<KCODE, 256>>>(emb, eprob, out);
    fin_kernel<<<1, 1>>>(out);
}

// round 6
// speedup vs baseline: 2.4630x; 1.1720x over previous
#include <cuda_runtime.h>
#include <math.h>
#include <stdint.h>

// Problem constants
#define NFEAT 16384          // B*H*W = 16*32*32
#define KCODE 8192           // codebook size
#define CDIM  256            // codebook dim
#define BATCH 16
#define HDIM  32
#define WDIM  32

// Output layout (float32, concatenated in reference tuple order)
#define OUT_ZQ    0
#define OUT_LOSS  4194304
#define OUT_QERR  4194305
#define OUT_UTIL  4194306
#define OUT_PERP  4194307
#define OUT_NEMB  4194308
#define OUT_NPROB 6291460

// GEMM tiling
#define BM 128
#define BN 256
#define NJB (KCODE / BN)     // 32 j-blocks
#define BK 32
#define LDK 40               // padded row (floats) -> conflict-free LDS.64
#define ROWB (LDK * 4)       // 160 bytes

// candidate window: must exceed 2*ulp(256) + 2*tf32_err  (~6.1e-5)
#define EPSB 8e-5f
#define MAXX (1 << 21)

// Scratch (device globals; no dynamic allocation allowed)
__device__ float              g_zf[NFEAT * CDIM];
__device__ float              g_S[NFEAT];
__device__ float              g_e2[KCODE];
__device__ unsigned long long g_blockmin[NFEAT][NJB];
__device__ unsigned long long g_exkey[NFEAT];
__device__ unsigned int       g_extras[MAXX];
__device__ unsigned int       g_xcnt;
__device__ unsigned long long g_maxkey[KCODE];
__device__ unsigned int       g_hist[KCODE];
__device__ int                g_token[NFEAT];
__device__ float              g_sse;
__device__ float              g_ent;
__device__ unsigned int       g_util;

__device__ __forceinline__ unsigned int ford(float f) {
    unsigned int u = __float_as_uint(f);
    return u ^ ((((int)u) >> 31) | 0x80000000u);
}
__device__ __forceinline__ float unford(unsigned int u) {
    unsigned int v = (u & 0x80000000u) ? (u ^ 0x80000000u) : ~u;
    return __uint_as_float(v);
}

// exact distance on the reference fp32 grid, via compensated fp32 dot
// (TwoProdFMA + TwoSum, abs error ~1e-15 -- no FP64 instructions).
// Warp-cooperative; all lanes return the same value.
__device__ __forceinline__ float exact_d32(const float* __restrict__ emb,
                                           int n, int j, int lane) {
    const float* zr = g_zf + (size_t)n * CDIM;
    const float* er = emb + (size_t)j * CDIM;
    float hi = 0.0f, lo = 0.0f;
#pragma unroll
    for (int c = 0; c < CDIM / 32; c++) {
        float a = zr[lane + 32 * c], b = er[lane + 32 * c];
        float p = __fmul_rn(a, b);
        float perr = fmaf(a, b, -p);
        float s = __fadd_rn(hi, p);
        float bp = __fsub_rn(s, hi);
        float e = __fadd_rn(__fsub_rn(hi, __fsub_rn(s, bp)), __fsub_rn(p, bp));
        hi = s;
        lo = __fadd_rn(lo, __fadd_rn(e, perr));
    }
#pragma unroll
    for (int m = 16; m; m >>= 1) {
        float oh = __shfl_xor_sync(0xffffffffu, hi, m);
        float ol = __shfl_xor_sync(0xffffffffu, lo, m);
        float s = __fadd_rn(hi, oh);
        float bp = __fsub_rn(s, hi);
        float e = __fadd_rn(__fsub_rn(hi, __fsub_rn(s, bp)), __fsub_rn(oh, bp));
        hi = s;
        lo = __fadd_rn(__fadd_rn(lo, ol), e);
    }
    float dotf = __fadd_rn(hi, lo);
    return __fsub_rn(__fadd_rn(g_S[n], g_e2[j]), 2.0f * dotf);
}

// ---------------------------------------------------------------------------
// K0: init scratch
// ---------------------------------------------------------------------------
__global__ void init_kernel() {
    int i = blockIdx.x * blockDim.x + threadIdx.x;
    if (i < NFEAT) g_exkey[i] = ~0ull;
    if (i < KCODE) { g_maxkey[i] = ~0ull; g_hist[i] = 0u; }
    if (i == 0) { g_sse = 0.0f; g_ent = 0.0f; g_util = 0u; g_xcnt = 0u; }
}

// ---------------------------------------------------------------------------
// K1: transpose z -> zf, compute S
// ---------------------------------------------------------------------------
__global__ void __launch_bounds__(256) prep_kernel(const float* __restrict__ z) {
    __shared__ float tile[32][CDIM + 1];
    int tid = threadIdx.x;
    int tx = tid & 31, ty = tid >> 5;
    int b = blockIdx.x >> 5, h = blockIdx.x & 31;
    const float* zp = z + (size_t)b * (CDIM * HDIM * WDIM) + h * WDIM;
#pragma unroll
    for (int i = 0; i < 32; i++) {
        int c = i * 8 + ty;
        tile[tx][c] = zp[c * (HDIM * WDIM) + tx];
    }
    __syncthreads();
    int nbase = b * 1024 + h * 32;
#pragma unroll
    for (int j = 0; j < 4; j++) {
        int w = ty * 4 + j;
        int n = nbase + w;
        float s = 0.0f;
#pragma unroll
        for (int i = 0; i < 8; i++) {
            int c = tx + 32 * i;
            float v = tile[w][c];
            g_zf[(size_t)n * CDIM + c] = v;
            s += v * v;
        }
#pragma unroll
        for (int m = 16; m; m >>= 1) s += __shfl_xor_sync(0xffffffffu, s, m);
        if (tx == 0) g_S[n] = s;
    }
}

// ---------------------------------------------------------------------------
// K2: e2
// ---------------------------------------------------------------------------
__global__ void __launch_bounds__(256) e2_kernel(const float* __restrict__ emb) {
    int tid = threadIdx.x;
    int tx = tid & 31, ty = tid >> 5;
    int j = blockIdx.x * 8 + ty;
    float s = 0.0f;
#pragma unroll
    for (int i = 0; i < 8; i++) {
        float v = emb[(size_t)j * CDIM + tx + 32 * i];
        s += v * v;
    }
#pragma unroll
    for (int m = 16; m; m >>= 1) s += __shfl_xor_sync(0xffffffffu, s, m);
    if (tx == 0) g_e2[j] = s;
}

// ---------------------------------------------------------------------------
// K3: tf32 mma GEMM (512 threads, 16 warps 2Mx8N, warp tile 64x32)
// ---------------------------------------------------------------------------
#define SM_ROWKEY 0             // 128 u64
#define SM_COLKEY 1024          // 256 u64
#define SM_SS     3072          // 128 f
#define SM_E2S    3584          // 256 f
#define SM_DATA   4608
#define STAGE_A   (BM * ROWB)               // 20480
#define STAGE_B   (BN * ROWB)               // 40960
#define STAGE_SZ  (STAGE_A + STAGE_B)       // 61440
#define NSTAGE 3
#define GEMM_SMEM (SM_DATA + NSTAGE * STAGE_SZ)   // 188928

__device__ __forceinline__ void cpa16(uint32_t dst, const void* src) {
    asm volatile("cp.async.cg.shared.global [%0], [%1], 16;"
                 :: "r"(dst), "l"(src));
}

#define MMA8(d, a0, a1, a2, a3, b0, b1)                                      \
    asm volatile(                                                            \
        "mma.sync.aligned.m16n8k8.row.col.f32.tf32.tf32.f32 "                \
        "{%0,%1,%2,%3},{%4,%5,%6,%7},{%8,%9},{%0,%1,%2,%3};"                 \
        : "+f"(d[0]), "+f"(d[1]), "+f"(d[2]), "+f"(d[3])                     \
        : "r"(a0), "r"(a1), "r"(a2), "r"(a3), "r"(b0), "r"(b1))

extern __shared__ char dynsmem[];

__global__ void __launch_bounds__(512, 1)
gemm_mma_kernel(const float* __restrict__ emb) {
    const int tid  = threadIdx.x;
    const int lane = tid & 31;
    const int warp = tid >> 5;
    const int gid  = lane >> 2;     // 0..7
    const int tig  = lane & 3;      // 0..3
    const int wm   = warp >> 3;     // 0..1
    const int wn   = warp & 7;      // 0..7
    const int m0   = blockIdx.y * BM;
    const int j0   = blockIdx.x * BN;

    unsigned long long* rowkey = (unsigned long long*)(dynsmem + SM_ROWKEY);
    unsigned long long* colkey = (unsigned long long*)(dynsmem + SM_COLKEY);
    float* Ss  = (float*)(dynsmem + SM_SS);
    float* e2s = (float*)(dynsmem + SM_E2S);

    uint32_t smbase;
    asm("{ .reg .u64 t; cvta.to.shared.u64 t, %1; cvt.u32.u64 %0, t; }"
        : "=r"(smbase) : "l"(dynsmem));

    const int t8 = tid >> 3;
    const int c8 = tid & 7;
    const float* gA0 = g_zf + (size_t)(m0 + t8) * CDIM + c8 * 4;
    const float* gB0 = emb  + (size_t)(j0 + t8) * CDIM + c8 * 4;
    const uint32_t dA0 = smbase + SM_DATA + t8 * ROWB + c8 * 16;
    const uint32_t dB0 = dA0 + STAGE_A;

    auto load_kb = [&](int s, int kb) {
        uint32_t so = s * STAGE_SZ;
        const float* ga = gA0 + kb * BK;
        const float* gb = gB0 + kb * BK;
#pragma unroll
        for (int i = 0; i < 2; i++)
            cpa16(dA0 + so + i * 64 * ROWB, ga + (size_t)i * 64 * CDIM);
#pragma unroll
        for (int i = 0; i < 4; i++)
            cpa16(dB0 + so + i * 64 * ROWB, gb + (size_t)i * 64 * CDIM);
    };

    if (tid < 128) { rowkey[tid] = ~0ull; Ss[tid] = g_S[m0 + tid]; }
    if (tid < 256) { colkey[tid] = ~0ull; e2s[tid] = g_e2[j0 + tid]; }

    load_kb(0, 0);
    asm volatile("cp.async.commit_group;" ::: "memory");
    load_kb(1, 1);
    asm volatile("cp.async.commit_group;" ::: "memory");

    float acc[4][4][4];
#pragma unroll
    for (int nt = 0; nt < 4; nt++)
#pragma unroll
        for (int mt = 0; mt < 4; mt++)
#pragma unroll
            for (int c = 0; c < 4; c++) acc[nt][mt][c] = 0.0f;

    const int aBase2 = (wm * 64 + gid) * (LDK / 2) + tig;
    const int bBase2 = (wn * 32 + gid) * (LDK / 2) + tig;

#pragma unroll 1
    for (int kb = 0; kb < 8; kb++) {
        if (kb + 2 < 8) load_kb((kb + 2) % NSTAGE, kb + 2);
        asm volatile("cp.async.commit_group;" ::: "memory");
        asm volatile("cp.async.wait_group 2;" ::: "memory");
        __syncthreads();

        const uint2* Af2 =
            (const uint2*)(dynsmem + SM_DATA + (kb % NSTAGE) * STAGE_SZ);
        const uint2* Bf2 = Af2 + STAGE_A / 8;

#pragma unroll
        for (int ks = 0; ks < 4; ks++) {
            const int ko = ks * 4;
            uint2 alo[4], ahi[4], bv[4];
#pragma unroll
            for (int mt = 0; mt < 4; mt++) {
                int o = aBase2 + mt * 16 * (LDK / 2) + ko;
                alo[mt] = Af2[o];
                ahi[mt] = Af2[o + 8 * (LDK / 2)];
            }
#pragma unroll
            for (int nt = 0; nt < 4; nt++)
                bv[nt] = Bf2[bBase2 + nt * 8 * (LDK / 2) + ko];
#pragma unroll
            for (int nt = 0; nt < 4; nt++)
#pragma unroll
                for (int mt = 0; mt < 4; mt++)
                    MMA8(acc[nt][mt], alo[mt].x, ahi[mt].x,
                         alo[mt].y, ahi[mt].y, bv[nt].x, bv[nt].y);
        }
        __syncthreads();
    }

    // ---- epilogue pass 1: approx argmin (row, float) + argmax (col, float)
    float S_lo[4], S_hi[4];
#pragma unroll
    for (int mt = 0; mt < 4; mt++) {
        S_lo[mt] = Ss[wm * 64 + mt * 16 + gid];
        S_hi[mt] = Ss[wm * 64 + mt * 16 + gid + 8];
    }
    float bd_lo[4], bd_hi[4];
    int   bj_lo[4], bj_hi[4];
#pragma unroll
    for (int mt = 0; mt < 4; mt++) {
        bd_lo[mt] = __int_as_float(0x7f800000); bj_lo[mt] = 0;
        bd_hi[mt] = __int_as_float(0x7f800000); bj_hi[mt] = 0;
    }

#pragma unroll
    for (int nt = 0; nt < 4; nt++) {
        const int ca = wn * 32 + nt * 8 + 2 * tig;
        const float e2a = e2s[ca], e2b = e2s[ca + 1];
        const int ja = j0 + ca;
        float cva = __int_as_float(0xff800000), cvb = cva;   // -inf
        int cia = 0, cib = 0;
#pragma unroll
        for (int mt = 0; mt < 4; mt++) {
            const int rlo = m0 + wm * 64 + mt * 16 + gid;
            float d00 = fmaf(-2.0f, acc[nt][mt][0], S_lo[mt] + e2a);
            float d01 = fmaf(-2.0f, acc[nt][mt][1], S_lo[mt] + e2b);
            float d10 = fmaf(-2.0f, acc[nt][mt][2], S_hi[mt] + e2a);
            float d11 = fmaf(-2.0f, acc[nt][mt][3], S_hi[mt] + e2b);
            // row argmin: strict <, columns visited in ascending j order
            if (d00 < bd_lo[mt]) { bd_lo[mt] = d00; bj_lo[mt] = ja; }
            if (d01 < bd_lo[mt]) { bd_lo[mt] = d01; bj_lo[mt] = ja + 1; }
            if (d10 < bd_hi[mt]) { bd_hi[mt] = d10; bj_hi[mt] = ja; }
            if (d11 < bd_hi[mt]) { bd_hi[mt] = d11; bj_hi[mt] = ja + 1; }
            // col argmax: strict >, rows visited in ascending order per thread
            if (d00 > cva) { cva = d00; cia = rlo; }
            if (d10 > cva) { cva = d10; cia = rlo + 8; }
            if (d01 > cvb) { cvb = d01; cib = rlo; }
            if (d11 > cvb) { cvb = d11; cib = rlo + 8; }
        }
        // merge (val, idx) over gid lanes; tie -> lower row index
#pragma unroll
        for (int off = 4; off < 32; off <<= 1) {
            float ov = __shfl_xor_sync(0xffffffffu, cva, off);
            int   oi = __shfl_xor_sync(0xffffffffu, cia, off);
            if (ov > cva || (ov == cva && oi < cia)) { cva = ov; cia = oi; }
            ov = __shfl_xor_sync(0xffffffffu, cvb, off);
            oi = __shfl_xor_sync(0xffffffffu, cib, off);
            if (ov > cvb || (ov == cvb && oi < cib)) { cvb = ov; cib = oi; }
        }
        if (gid == 0) {
            atomicMin(&colkey[ca],
                      (((unsigned long long)(~ford(cva))) << 32) | (unsigned)cia);
            atomicMin(&colkey[ca + 1],
                      (((unsigned long long)(~ford(cvb))) << 32) | (unsigned)cib);
        }
    }
#pragma unroll
    for (int mt = 0; mt < 4; mt++) {
        unsigned long long klo =
            (((unsigned long long)ford(bd_lo[mt])) << 32) | (unsigned)bj_lo[mt];
        unsigned long long khi =
            (((unsigned long long)ford(bd_hi[mt])) << 32) | (unsigned)bj_hi[mt];
#pragma unroll
        for (int off = 1; off < 4; off <<= 1) {
            klo = min(klo, __shfl_xor_sync(0xffffffffu, klo, off));
            khi = min(khi, __shfl_xor_sync(0xffffffffu, khi, off));
        }
        if (tig == 0) {
            atomicMin(&rowkey[wm * 64 + mt * 16 + gid], klo);
            atomicMin(&rowkey[wm * 64 + mt * 16 + gid + 8], khi);
        }
    }
    __syncthreads();

    if (tid < 128) g_blockmin[m0 + tid][blockIdx.x] = rowkey[tid];
    if (tid < 256) atomicMin(&g_maxkey[j0 + tid], colkey[tid]);

    // ---- epilogue pass 2: append near-tie candidates ----
#pragma unroll
    for (int mt = 0; mt < 4; mt++) {
        const int rl = wm * 64 + mt * 16 + gid;
        const int rh = rl + 8;
        const unsigned long long rkl = rowkey[rl];
        const unsigned long long rkh = rowkey[rh];
        const float vl = unford((unsigned)(rkl >> 32)) + EPSB;
        const float vh = unford((unsigned)(rkh >> 32)) + EPSB;
#pragma unroll
        for (int nt = 0; nt < 4; nt++) {
            const int ca = wn * 32 + nt * 8 + 2 * tig;
            const float e2a = e2s[ca], e2b = e2s[ca + 1];
            const unsigned ja = (unsigned)(j0 + ca);
            float d00 = fmaf(-2.0f, acc[nt][mt][0], S_lo[mt] + e2a);
            float d01 = fmaf(-2.0f, acc[nt][mt][1], S_lo[mt] + e2b);
            float d10 = fmaf(-2.0f, acc[nt][mt][2], S_hi[mt] + e2a);
            float d11 = fmaf(-2.0f, acc[nt][mt][3], S_hi[mt] + e2b);
            if (d00 < vl) {
                unsigned long long k = (((unsigned long long)ford(d00)) << 32) | ja;
                if (k != rkl) {
                    unsigned slot = atomicAdd(&g_xcnt, 1u);
                    if (slot < MAXX)
                        g_extras[slot] = ((unsigned)(m0 + rl) << 13) | ja;
                }
            }
            if (d01 < vl) {
                unsigned long long k = (((unsigned long long)ford(d01)) << 32) | (ja + 1);
                if (k != rkl) {
                    unsigned slot = atomicAdd(&g_xcnt, 1u);
                    if (slot < MAXX)
                        g_extras[slot] = ((unsigned)(m0 + rl) << 13) | (ja + 1);
                }
            }
            if (d10 < vh) {
                unsigned long long k = (((unsigned long long)ford(d10)) << 32) | ja;
                if (k != rkh) {
                    unsigned slot = atomicAdd(&g_xcnt, 1u);
                    if (slot < MAXX)
                        g_extras[slot] = ((unsigned)(m0 + rh) << 13) | ja;
                }
            }
            if (d11 < vh) {
                unsigned long long k = (((unsigned long long)ford(d11)) << 32) | (ja + 1);
                if (k != rkh) {
                    unsigned slot = atomicAdd(&g_xcnt, 1u);
                    if (slot < MAXX)
                        g_extras[slot] = ((unsigned)(m0 + rh) << 13) | (ja + 1);
                }
            }
        }
    }
}

// ---------------------------------------------------------------------------
// K4a: exact recompute of appended extras
// ---------------------------------------------------------------------------
__global__ void __launch_bounds__(256) extras_kernel(const float* __restrict__ emb) {
    const unsigned cnt = min(g_xcnt, (unsigned)MAXX);
    const int lane = threadIdx.x & 31;
    const int wid = (blockIdx.x * blockDim.x + threadIdx.x) >> 5;
    const int nw = (gridDim.x * blockDim.x) >> 5;
    for (unsigned i = wid; i < cnt; i += nw) {
        unsigned e = g_extras[i];
        int n = e >> 13;
        int j = e & 8191;
        float d32 = exact_d32(emb, n, j, lane);
        unsigned long long key =
            (((unsigned long long)ford(d32)) << 32) | (unsigned)j;
        if (lane == 0) atomicMin(&g_exkey[n], key);
    }
}

// ---------------------------------------------------------------------------
// K4b: per-row token resolution (+ histogram)
// ---------------------------------------------------------------------------
__global__ void __launch_bounds__(256) tokenfix_kernel(const float* __restrict__ emb) {
    const int lane = threadIdx.x & 31;
    const int wid = (blockIdx.x * blockDim.x + threadIdx.x) >> 5;
    const int nw = (gridDim.x * blockDim.x) >> 5;
    for (int n = wid; n < NFEAT; n += nw) {
        unsigned long long k = g_blockmin[n][lane];   // NJB == 32
        unsigned long long gm = k;
#pragma unroll
        for (int m = 16; m; m >>= 1)
            gm = min(gm, __shfl_xor_sync(0xffffffffu, gm, m));
        float thresh = unford((unsigned)(gm >> 32)) + EPSB;
        bool cand = unford((unsigned)(k >> 32)) < thresh;
        unsigned bal = __ballot_sync(0xffffffffu, cand);
        unsigned long long ex = g_exkey[n];
        unsigned tok;
        if (__popc(bal) == 1 && ex == ~0ull) {
            tok = (unsigned)(gm & 0xffffffffull);
        } else {
            unsigned long long best = ex;
            unsigned b = bal;
            while (b) {
                int src = __ffs(b) - 1;
                b &= b - 1;
                unsigned jj = __shfl_sync(0xffffffffu,
                                          (unsigned)(k & 0xffffffffull), src);
                float d32 = exact_d32(emb, n, (int)jj, lane);
                unsigned long long key =
                    (((unsigned long long)ford(d32)) << 32) | jj;
                best = min(best, key);
            }
            tok = (unsigned)(best & 0xffffffffull);
        }
        if (lane == 0) {
            g_token[n] = (int)tok;
            atomicAdd(&g_hist[tok], 1u);
        }
    }
}

// ---------------------------------------------------------------------------
// K5: z_q straight-through output + SSE
// ---------------------------------------------------------------------------
__global__ void __launch_bounds__(256) zq_kernel(const float* __restrict__ emb,
                                                 float* __restrict__ out) {
    __shared__ float rowbuf[32][CDIM + 1];
    __shared__ int stok[32];
    __shared__ float red[8];
    int tid = threadIdx.x;
    int b = blockIdx.x >> 5, h = blockIdx.x & 31;
    int nbase = b * 1024 + h * 32;
    if (tid < 32) stok[tid] = g_token[nbase + tid];
    __syncthreads();
    float acc = 0.0f;
#pragma unroll 4
    for (int w = 0; w < 32; w++) {
        float v  = emb[(size_t)stok[w] * CDIM + tid];
        float zv = g_zf[(size_t)(nbase + w) * CDIM + tid];
        float diff = __fsub_rn(v, zv);
        acc = fmaf(diff, diff, acc);
        rowbuf[w][tid] = __fadd_rn(zv, diff);
    }
    float s = acc;
#pragma unroll
    for (int m = 16; m; m >>= 1) s += __shfl_xor_sync(0xffffffffu, s, m);
    if ((tid & 31) == 0) red[tid >> 5] = s;
    __syncthreads();
    if (tid == 0) {
        float t = 0.0f;
#pragma unroll
        for (int i = 0; i < 8; i++) t += red[i];
        atomicAdd(&g_sse, t);
    }
    int tx = tid & 31, ty = tid >> 5;
#pragma unroll
    for (int i = 0; i < 32; i++) {
        int c = i * 8 + ty;
        out[OUT_ZQ + (((size_t)b * CDIM + c) * HDIM + h) * WDIM + tx] = rowbuf[tx][c];
    }
}

// ---------------------------------------------------------------------------
// K6: per-code update
// ---------------------------------------------------------------------------
__global__ void __launch_bounds__(256) code_kernel(const float* __restrict__ emb,
                                                   const float* __restrict__ eprob,
                                                   float* __restrict__ out) {
    int j = blockIdx.x;
    int c = threadIdx.x;
    unsigned hcnt = g_hist[j];
    float avg = (float)hcnt * (1.0f / 16384.0f);
    float np  = __fadd_rn(__fmul_rn(eprob[j], 0.99f), __fmul_rn(avg, 0.01f));
    float t = __fmul_rn(np, 8192.0f);
    t = __fmul_rn(t, 10.0f);
    t = __fdiv_rn(t, 0.01f);
    float decay = expf(-t - 0.001f);
    float omd = __fsub_rn(1.0f, decay);
    if (c == 0) {
        out[OUT_NPROB + j] = np;
        atomicAdd(&g_ent, avg * logf(avg + 1e-10f));
        if (hcnt > 0) atomicAdd(&g_util, 1u);
    }
    int fi = (int)(g_maxkey[j] & 0xffffffffull);
    float rf = g_zf[(size_t)fi * CDIM + c];
    float e  = emb[(size_t)j * CDIM + c];
    out[OUT_NEMB + (size_t)j * CDIM + c] =
        __fadd_rn(__fmul_rn(e, omd), __fmul_rn(rf, decay));
}

// ---------------------------------------------------------------------------
// K7: finalize scalars
// ---------------------------------------------------------------------------
__global__ void fin_kernel(float* __restrict__ out) {
    float sse = g_sse;
    float mse = sse / 4194304.0f;
    out[OUT_LOSS] = __fadd_rn(__fmul_rn(0.25f, mse), mse);
    out[OUT_QERR] = sse / 16384.0f;
    out[OUT_UTIL] = (float)g_util / 8192.0f;
    out[OUT_PERP] = expf(-g_ent);
}

// ---------------------------------------------------------------------------
extern "C" void kernel_launch(void* const* d_in, const int* in_sizes, int n_in,
                              void* d_out, int out_size) {
    (void)in_sizes; (void)n_in; (void)out_size;
    const float* z     = (const float*)d_in[0];
    const float* emb   = (const float*)d_in[1];
    const float* eprob = (const float*)d_in[2];
    float* out = (float*)d_out;

    static int smem_set = 0;
    if (!smem_set) {
        cudaFuncSetAttribute(gemm_mma_kernel,
                             cudaFuncAttributeMaxDynamicSharedMemorySize,
                             GEMM_SMEM);
        smem_set = 1;
    }

    init_kernel<<<64, 256>>>();
    prep_kernel<<<BATCH * HDIM, 256>>>(z);
    e2_kernel<<<KCODE / 8, 256>>>(emb);
    gemm_mma_kernel<<<dim3(NJB, NFEAT / BM), 512, GEMM_SMEM>>>(emb);
    extras_kernel<<<256, 256>>>(emb);
    tokenfix_kernel<<<256, 256>>>(emb);
    zq_kernel<<<BATCH * HDIM, 256>>>(emb, out);
    code_kernel<<<KCODE, 256>>>(emb, eprob, out);
    fin_kernel<<<1, 1>>>(out);
}

// round 7
// speedup vs baseline: 3.2994x; 1.3395x over previous
#include <cuda_runtime.h>
#include <cuda_fp16.h>
#include <math.h>
#include <stdint.h>

// Problem constants
#define NFEAT 16384          // B*H*W = 16*32*32
#define KCODE 8192           // codebook size
#define CDIM  256            // codebook dim
#define BATCH 16
#define HDIM  32
#define WDIM  32

// Output layout (float32, concatenated in reference tuple order)
#define OUT_ZQ    0
#define OUT_LOSS  4194304
#define OUT_QERR  4194305
#define OUT_UTIL  4194306
#define OUT_PERP  4194307
#define OUT_NEMB  4194308
#define OUT_NPROB 6291460

// GEMM tiling (fp16 m16n8k16 path)
#define BM 128
#define BN 256
#define NJB (KCODE / BN)     // 32 j-blocks
#define BK 64                // fp16 k-chunk per stage
#define NKB (CDIM / BK)      // 4
#define LDKH 80              // padded row in halves (160 B) -> stride 8 banks/row
#define ROWB (LDKH * 2)      // 160 bytes

// codebook pre-scale 2^14 (exact); epilogue rescale -2*2^-14 = -2^-13
#define ESCALE 16384.0f
#define DSCALE (-1.0f / 8192.0f)

// candidate window: > 2*ulp(256) + 2*fp16_approx_err
#define EPSB 1.2e-4f
#define MAXX (1 << 21)

// Scratch (device globals; no dynamic allocation allowed)
__device__ float              g_zf[NFEAT * CDIM];
__device__ __half             g_zh[NFEAT * CDIM];
__device__ __half             g_eh[KCODE * CDIM];   // embedding * 2^14, fp16
__device__ float              g_S[NFEAT];
__device__ float              g_e2[KCODE];
__device__ unsigned long long g_blockmin[NFEAT][NJB];
__device__ unsigned long long g_exkey[NFEAT];
__device__ unsigned int       g_extras[MAXX];
__device__ unsigned int       g_xcnt;
__device__ unsigned long long g_maxkey[KCODE];
__device__ unsigned int       g_hist[KCODE];
__device__ int                g_token[NFEAT];
__device__ float              g_sse;
__device__ float              g_ent;
__device__ unsigned int       g_util;

__device__ __forceinline__ unsigned int ford(float f) {
    unsigned int u = __float_as_uint(f);
    return u ^ ((((int)u) >> 31) | 0x80000000u);
}
__device__ __forceinline__ float unford(unsigned int u) {
    unsigned int v = (u & 0x80000000u) ? (u ^ 0x80000000u) : ~u;
    return __uint_as_float(v);
}

// exact distance on the reference fp32 grid, via compensated fp32 dot
// (TwoProdFMA + TwoSum). Warp-cooperative; all lanes return the same value.
__device__ __forceinline__ float exact_d32(const float* __restrict__ emb,
                                           int n, int j, int lane) {
    const float* zr = g_zf + (size_t)n * CDIM;
    const float* er = emb + (size_t)j * CDIM;
    float hi = 0.0f, lo = 0.0f;
#pragma unroll
    for (int c = 0; c < CDIM / 32; c++) {
        float a = zr[lane + 32 * c], b = er[lane + 32 * c];
        float p = __fmul_rn(a, b);
        float perr = fmaf(a, b, -p);
        float s = __fadd_rn(hi, p);
        float bp = __fsub_rn(s, hi);
        float e = __fadd_rn(__fsub_rn(hi, __fsub_rn(s, bp)), __fsub_rn(p, bp));
        hi = s;
        lo = __fadd_rn(lo, __fadd_rn(e, perr));
    }
#pragma unroll
    for (int m = 16; m; m >>= 1) {
        float oh = __shfl_xor_sync(0xffffffffu, hi, m);
        float ol = __shfl_xor_sync(0xffffffffu, lo, m);
        float s = __fadd_rn(hi, oh);
        float bp = __fsub_rn(s, hi);
        float e = __fadd_rn(__fsub_rn(hi, __fsub_rn(s, bp)), __fsub_rn(oh, bp));
        hi = s;
        lo = __fadd_rn(__fadd_rn(lo, ol), e);
    }
    float dotf = __fadd_rn(hi, lo);
    return __fsub_rn(__fadd_rn(g_S[n], g_e2[j]), 2.0f * dotf);
}

// ---------------------------------------------------------------------------
// K0: init scratch
// ---------------------------------------------------------------------------
__global__ void init_kernel() {
    int i = blockIdx.x * blockDim.x + threadIdx.x;
    if (i < NFEAT) g_exkey[i] = ~0ull;
    if (i < KCODE) { g_maxkey[i] = ~0ull; g_hist[i] = 0u; }
    if (i == 0) { g_sse = 0.0f; g_ent = 0.0f; g_util = 0u; g_xcnt = 0u; }
}

// ---------------------------------------------------------------------------
// K1: transpose z -> zf (fp32 + fp16), compute S
// ---------------------------------------------------------------------------
__global__ void __launch_bounds__(256) prep_kernel(const float* __restrict__ z) {
    __shared__ float tile[32][CDIM + 1];
    int tid = threadIdx.x;
    int tx = tid & 31, ty = tid >> 5;
    int b = blockIdx.x >> 5, h = blockIdx.x & 31;
    const float* zp = z + (size_t)b * (CDIM * HDIM * WDIM) + h * WDIM;
#pragma unroll
    for (int i = 0; i < 32; i++) {
        int c = i * 8 + ty;
        tile[tx][c] = zp[c * (HDIM * WDIM) + tx];
    }
    __syncthreads();
    int nbase = b * 1024 + h * 32;
#pragma unroll
    for (int j = 0; j < 4; j++) {
        int w = ty * 4 + j;
        int n = nbase + w;
        float s = 0.0f;
#pragma unroll
        for (int i = 0; i < 8; i++) {
            int c = tx + 32 * i;
            float v = tile[w][c];
            g_zf[(size_t)n * CDIM + c] = v;
            g_zh[(size_t)n * CDIM + c] = __float2half_rn(v);
            s += v * v;
        }
#pragma unroll
        for (int m = 16; m; m >>= 1) s += __shfl_xor_sync(0xffffffffu, s, m);
        if (tx == 0) g_S[n] = s;
    }
}

// ---------------------------------------------------------------------------
// K2: e2 + fp16 scaled copy
// ---------------------------------------------------------------------------
__global__ void __launch_bounds__(256) e2_kernel(const float* __restrict__ emb) {
    int tid = threadIdx.x;
    int tx = tid & 31, ty = tid >> 5;
    int j = blockIdx.x * 8 + ty;
    float s = 0.0f;
#pragma unroll
    for (int i = 0; i < 8; i++) {
        float v = emb[(size_t)j * CDIM + tx + 32 * i];
        g_eh[(size_t)j * CDIM + tx + 32 * i] = __float2half_rn(v * ESCALE);
        s += v * v;
    }
#pragma unroll
    for (int m = 16; m; m >>= 1) s += __shfl_xor_sync(0xffffffffu, s, m);
    if (tx == 0) g_e2[j] = s;
}

// ---------------------------------------------------------------------------
// K3: fp16 m16n8k16 mma GEMM (512 threads, 16 warps 2Mx8N, warp tile 64x32)
// k-slot re-pairing: both A and B feed phys k = 4*tig..4*tig+3 into the
// instruction's (reg0/reg2 | b0/b1) slots -> all fragments load as LDS.64.
// D-fragment layout identical to m16n8k8 -> epilogue unchanged.
// ---------------------------------------------------------------------------
#define SM_ROWKEY 0             // 128 u64
#define SM_COLKEY 1024          // 256 u64
#define SM_SS     3072          // 128 f
#define SM_E2S    3584          // 256 f
#define SM_DATA   4608
#define STAGE_A   (BM * ROWB)               // 20480
#define STAGE_B   (BN * ROWB)               // 40960
#define STAGE_SZ  (STAGE_A + STAGE_B)       // 61440
#define NSTAGE 3
#define GEMM_SMEM (SM_DATA + NSTAGE * STAGE_SZ)   // 188928

__device__ __forceinline__ void cpa16(uint32_t dst, const void* src) {
    asm volatile("cp.async.cg.shared.global [%0], [%1], 16;"
                 :: "r"(dst), "l"(src));
}

#define MMA16(d, a0, a1, a2, a3, b0, b1)                                     \
    asm volatile(                                                            \
        "mma.sync.aligned.m16n8k16.row.col.f32.f16.f16.f32 "                 \
        "{%0,%1,%2,%3},{%4,%5,%6,%7},{%8,%9},{%0,%1,%2,%3};"                 \
        : "+f"(d[0]), "+f"(d[1]), "+f"(d[2]), "+f"(d[3])                     \
        : "r"(a0), "r"(a1), "r"(a2), "r"(a3), "r"(b0), "r"(b1))

extern __shared__ char dynsmem[];

__global__ void __launch_bounds__(512, 1)
gemm_mma_kernel(const float* __restrict__ emb) {
    const int tid  = threadIdx.x;
    const int lane = tid & 31;
    const int warp = tid >> 5;
    const int gid  = lane >> 2;     // 0..7
    const int tig  = lane & 3;      // 0..3
    const int wm   = warp >> 3;     // 0..1
    const int wn   = warp & 7;      // 0..7
    const int m0   = blockIdx.y * BM;
    const int j0   = blockIdx.x * BN;

    unsigned long long* rowkey = (unsigned long long*)(dynsmem + SM_ROWKEY);
    unsigned long long* colkey = (unsigned long long*)(dynsmem + SM_COLKEY);
    float* Ss  = (float*)(dynsmem + SM_SS);
    float* e2s = (float*)(dynsmem + SM_E2S);

    uint32_t smbase;
    asm("{ .reg .u64 t; cvta.to.shared.u64 t, %1; cvt.u32.u64 %0, t; }"
        : "=r"(smbase) : "l"(dynsmem));

    // staging: BK=64 halves = 128 B = 8 x 16B segments per row
    const int t8 = tid >> 3;            // 0..63
    const int c8 = tid & 7;             // 0..7
    const __half* gA0 = g_zh + (size_t)(m0 + t8) * CDIM + c8 * 8;
    const __half* gB0 = g_eh + (size_t)(j0 + t8) * CDIM + c8 * 8;
    const uint32_t dA0 = smbase + SM_DATA + t8 * ROWB + c8 * 16;
    const uint32_t dB0 = dA0 + STAGE_A;

    auto load_kb = [&](int s, int kb) {
        uint32_t so = s * STAGE_SZ;
        const __half* ga = gA0 + kb * BK;
        const __half* gb = gB0 + kb * BK;
#pragma unroll
        for (int i = 0; i < 2; i++)
            cpa16(dA0 + so + i * 64 * ROWB, ga + (size_t)i * 64 * CDIM);
#pragma unroll
        for (int i = 0; i < 4; i++)
            cpa16(dB0 + so + i * 64 * ROWB, gb + (size_t)i * 64 * CDIM);
    };

    if (tid < 128) { rowkey[tid] = ~0ull; Ss[tid] = g_S[m0 + tid]; }
    if (tid < 256) { colkey[tid] = ~0ull; e2s[tid] = g_e2[j0 + tid]; }

    load_kb(0, 0);
    asm volatile("cp.async.commit_group;" ::: "memory");
    load_kb(1, 1);
    asm volatile("cp.async.commit_group;" ::: "memory");

    float acc[4][4][4];
#pragma unroll
    for (int nt = 0; nt < 4; nt++)
#pragma unroll
        for (int mt = 0; mt < 4; mt++)
#pragma unroll
            for (int c = 0; c < 4; c++) acc[nt][mt][c] = 0.0f;

    // fragment bases in uint2 (8B = 4 halves) units: row*(ROWB/8) + tig
    const int aBase2 = (wm * 64 + gid) * (ROWB / 8) + tig;
    const int bBase2 = (wn * 32 + gid) * (ROWB / 8) + tig;

#pragma unroll 1
    for (int kb = 0; kb < NKB; kb++) {
        if (kb + 2 < NKB) load_kb((kb + 2) % NSTAGE, kb + 2);
        asm volatile("cp.async.commit_group;" ::: "memory");
        asm volatile("cp.async.wait_group 2;" ::: "memory");
        __syncthreads();

        const uint2* Af2 =
            (const uint2*)(dynsmem + SM_DATA + (kb % NSTAGE) * STAGE_SZ);
        const uint2* Bf2 = Af2 + STAGE_A / 8;

#pragma unroll
        for (int ks = 0; ks < BK / 16; ks++) {        // 4 k16-steps
            const int ko = ks * 4;                    // 16 halves = 4 uint2
            uint2 alo[4], ahi[4], bv[4];
#pragma unroll
            for (int mt = 0; mt < 4; mt++) {
                int o = aBase2 + mt * 16 * (ROWB / 8) + ko;
                alo[mt] = Af2[o];                     // row gid:   a0, a2
                ahi[mt] = Af2[o + 8 * (ROWB / 8)];    // row gid+8: a1, a3
            }
#pragma unroll
            for (int nt = 0; nt < 4; nt++)
                bv[nt] = Bf2[bBase2 + nt * 8 * (ROWB / 8) + ko]; // b0, b1
#pragma unroll
            for (int nt = 0; nt < 4; nt++)
#pragma unroll
                for (int mt = 0; mt < 4; mt++)
                    MMA16(acc[nt][mt], alo[mt].x, ahi[mt].x,
                          alo[mt].y, ahi[mt].y, bv[nt].x, bv[nt].y);
        }
        __syncthreads();
    }

    // ---- epilogue pass 1: approx argmin (row) + argmax (col) ----
    float S_lo[4], S_hi[4];
#pragma unroll
    for (int mt = 0; mt < 4; mt++) {
        S_lo[mt] = Ss[wm * 64 + mt * 16 + gid];
        S_hi[mt] = Ss[wm * 64 + mt * 16 + gid + 8];
    }
    float bd_lo[4], bd_hi[4];
    int   bj_lo[4], bj_hi[4];
#pragma unroll
    for (int mt = 0; mt < 4; mt++) {
        bd_lo[mt] = __int_as_float(0x7f800000); bj_lo[mt] = 0;
        bd_hi[mt] = __int_as_float(0x7f800000); bj_hi[mt] = 0;
    }

#pragma unroll
    for (int nt = 0; nt < 4; nt++) {
        const int ca = wn * 32 + nt * 8 + 2 * tig;
        const float e2a = e2s[ca], e2b = e2s[ca + 1];
        const int ja = j0 + ca;
        float cva = __int_as_float(0xff800000), cvb = cva;   // -inf
        int cia = 0, cib = 0;
#pragma unroll
        for (int mt = 0; mt < 4; mt++) {
            const int rlo = m0 + wm * 64 + mt * 16 + gid;
            float d00 = fmaf(acc[nt][mt][0], DSCALE, S_lo[mt] + e2a);
            float d01 = fmaf(acc[nt][mt][1], DSCALE, S_lo[mt] + e2b);
            float d10 = fmaf(acc[nt][mt][2], DSCALE, S_hi[mt] + e2a);
            float d11 = fmaf(acc[nt][mt][3], DSCALE, S_hi[mt] + e2b);
            if (d00 < bd_lo[mt]) { bd_lo[mt] = d00; bj_lo[mt] = ja; }
            if (d01 < bd_lo[mt]) { bd_lo[mt] = d01; bj_lo[mt] = ja + 1; }
            if (d10 < bd_hi[mt]) { bd_hi[mt] = d10; bj_hi[mt] = ja; }
            if (d11 < bd_hi[mt]) { bd_hi[mt] = d11; bj_hi[mt] = ja + 1; }
            if (d00 > cva) { cva = d00; cia = rlo; }
            if (d10 > cva) { cva = d10; cia = rlo + 8; }
            if (d01 > cvb) { cvb = d01; cib = rlo; }
            if (d11 > cvb) { cvb = d11; cib = rlo + 8; }
        }
#pragma unroll
        for (int off = 4; off < 32; off <<= 1) {
            float ov = __shfl_xor_sync(0xffffffffu, cva, off);
            int   oi = __shfl_xor_sync(0xffffffffu, cia, off);
            if (ov > cva || (ov == cva && oi < cia)) { cva = ov; cia = oi; }
            ov = __shfl_xor_sync(0xffffffffu, cvb, off);
            oi = __shfl_xor_sync(0xffffffffu, cib, off);
            if (ov > cvb || (ov == cvb && oi < cib)) { cvb = ov; cib = oi; }
        }
        if (gid == 0) {
            atomicMin(&colkey[ca],
                      (((unsigned long long)(~ford(cva))) << 32) | (unsigned)cia);
            atomicMin(&colkey[ca + 1],
                      (((unsigned long long)(~ford(cvb))) << 32) | (unsigned)cib);
        }
    }
#pragma unroll
    for (int mt = 0; mt < 4; mt++) {
        unsigned long long klo =
            (((unsigned long long)ford(bd_lo[mt])) << 32) | (unsigned)bj_lo[mt];
        unsigned long long khi =
            (((unsigned long long)ford(bd_hi[mt])) << 32) | (unsigned)bj_hi[mt];
#pragma unroll
        for (int off = 1; off < 4; off <<= 1) {
            klo = min(klo, __shfl_xor_sync(0xffffffffu, klo, off));
            khi = min(khi, __shfl_xor_sync(0xffffffffu, khi, off));
        }
        if (tig == 0) {
            atomicMin(&rowkey[wm * 64 + mt * 16 + gid], klo);
            atomicMin(&rowkey[wm * 64 + mt * 16 + gid + 8], khi);
        }
    }
    __syncthreads();

    if (tid < 128) g_blockmin[m0 + tid][blockIdx.x] = rowkey[tid];
    if (tid < 256) atomicMin(&g_maxkey[j0 + tid], colkey[tid]);

    // ---- epilogue pass 2: append near-tie candidates ----
#pragma unroll
    for (int mt = 0; mt < 4; mt++) {
        const int rl = wm * 64 + mt * 16 + gid;
        const int rh = rl + 8;
        const unsigned long long rkl = rowkey[rl];
        const unsigned long long rkh = rowkey[rh];
        const float vl = unford((unsigned)(rkl >> 32)) + EPSB;
        const float vh = unford((unsigned)(rkh >> 32)) + EPSB;
#pragma unroll
        for (int nt = 0; nt < 4; nt++) {
            const int ca = wn * 32 + nt * 8 + 2 * tig;
            const float e2a = e2s[ca], e2b = e2s[ca + 1];
            const unsigned ja = (unsigned)(j0 + ca);
            float d00 = fmaf(acc[nt][mt][0], DSCALE, S_lo[mt] + e2a);
            float d01 = fmaf(acc[nt][mt][1], DSCALE, S_lo[mt] + e2b);
            float d10 = fmaf(acc[nt][mt][2], DSCALE, S_hi[mt] + e2a);
            float d11 = fmaf(acc[nt][mt][3], DSCALE, S_hi[mt] + e2b);
            if (d00 < vl) {
                unsigned long long k = (((unsigned long long)ford(d00)) << 32) | ja;
                if (k != rkl) {
                    unsigned slot = atomicAdd(&g_xcnt, 1u);
                    if (slot < MAXX)
                        g_extras[slot] = ((unsigned)(m0 + rl) << 13) | ja;
                }
            }
            if (d01 < vl) {
                unsigned long long k = (((unsigned long long)ford(d01)) << 32) | (ja + 1);
                if (k != rkl) {
                    unsigned slot = atomicAdd(&g_xcnt, 1u);
                    if (slot < MAXX)
                        g_extras[slot] = ((unsigned)(m0 + rl) << 13) | (ja + 1);
                }
            }
            if (d10 < vh) {
                unsigned long long k = (((unsigned long long)ford(d10)) << 32) | ja;
                if (k != rkh) {
                    unsigned slot = atomicAdd(&g_xcnt, 1u);
                    if (slot < MAXX)
                        g_extras[slot] = ((unsigned)(m0 + rh) << 13) | ja;
                }
            }
            if (d11 < vh) {
                unsigned long long k = (((unsigned long long)ford(d11)) << 32) | (ja + 1);
                if (k != rkh) {
                    unsigned slot = atomicAdd(&g_xcnt, 1u);
                    if (slot < MAXX)
                        g_extras[slot] = ((unsigned)(m0 + rh) << 13) | (ja + 1);
                }
            }
        }
    }
}

// ---------------------------------------------------------------------------
// K4a: exact recompute of appended extras
// ---------------------------------------------------------------------------
__global__ void __launch_bounds__(256) extras_kernel(const float* __restrict__ emb) {
    const unsigned cnt = min(g_xcnt, (unsigned)MAXX);
    const int lane = threadIdx.x & 31;
    const int wid = (blockIdx.x * blockDim.x + threadIdx.x) >> 5;
    const int nw = (gridDim.x * blockDim.x) >> 5;
    for (unsigned i = wid; i < cnt; i += nw) {
        unsigned e = g_extras[i];
        int n = e >> 13;
        int j = e & 8191;
        float d32 = exact_d32(emb, n, j, lane);
        unsigned long long key =
            (((unsigned long long)ford(d32)) << 32) | (unsigned)j;
        if (lane == 0) atomicMin(&g_exkey[n], key);
    }
}

// ---------------------------------------------------------------------------
// K4b: per-row token resolution (+ histogram)
// ---------------------------------------------------------------------------
__global__ void __launch_bounds__(256) tokenfix_kernel(const float* __restrict__ emb) {
    const int lane = threadIdx.x & 31;
    const int wid = (blockIdx.x * blockDim.x + threadIdx.x) >> 5;
    const int nw = (gridDim.x * blockDim.x) >> 5;
    for (int n = wid; n < NFEAT; n += nw) {
        unsigned long long k = g_blockmin[n][lane];   // NJB == 32
        unsigned long long gm = k;
#pragma unroll
        for (int m = 16; m; m >>= 1)
            gm = min(gm, __shfl_xor_sync(0xffffffffu, gm, m));
        float thresh = unford((unsigned)(gm >> 32)) + EPSB;
        bool cand = unford((unsigned)(k >> 32)) < thresh;
        unsigned bal = __ballot_sync(0xffffffffu, cand);
        unsigned long long ex = g_exkey[n];
        unsigned tok;
        if (__popc(bal) == 1 && ex == ~0ull) {
            tok = (unsigned)(gm & 0xffffffffull);
        } else {
            unsigned long long best = ex;
            unsigned b = bal;
            while (b) {
                int src = __ffs(b) - 1;
                b &= b - 1;
                unsigned jj = __shfl_sync(0xffffffffu,
                                          (unsigned)(k & 0xffffffffull), src);
                float d32 = exact_d32(emb, n, (int)jj, lane);
                unsigned long long key =
                    (((unsigned long long)ford(d32)) << 32) | jj;
                best = min(best, key);
            }
            tok = (unsigned)(best & 0xffffffffull);
        }
        if (lane == 0) {
            g_token[n] = (int)tok;
            atomicAdd(&g_hist[tok], 1u);
        }
    }
}

// ---------------------------------------------------------------------------
// K5: z_q straight-through output + SSE
// ---------------------------------------------------------------------------
__global__ void __launch_bounds__(256) zq_kernel(const float* __restrict__ emb,
                                                 float* __restrict__ out) {
    __shared__ float rowbuf[32][CDIM + 1];
    __shared__ int stok[32];
    __shared__ float red[8];
    int tid = threadIdx.x;
    int b = blockIdx.x >> 5, h = blockIdx.x & 31;
    int nbase = b * 1024 + h * 32;
    if (tid < 32) stok[tid] = g_token[nbase + tid];
    __syncthreads();
    float acc = 0.0f;
#pragma unroll 4
    for (int w = 0; w < 32; w++) {
        float v  = emb[(size_t)stok[w] * CDIM + tid];
        float zv = g_zf[(size_t)(nbase + w) * CDIM + tid];
        float diff = __fsub_rn(v, zv);
        acc = fmaf(diff, diff, acc);
        rowbuf[w][tid] = __fadd_rn(zv, diff);
    }
    float s = acc;
#pragma unroll
    for (int m = 16; m; m >>= 1) s += __shfl_xor_sync(0xffffffffu, s, m);
    if ((tid & 31) == 0) red[tid >> 5] = s;
    __syncthreads();
    if (tid == 0) {
        float t = 0.0f;
#pragma unroll
        for (int i = 0; i < 8; i++) t += red[i];
        atomicAdd(&g_sse, t);
    }
    int tx = tid & 31, ty = tid >> 5;
#pragma unroll
    for (int i = 0; i < 32; i++) {
        int c = i * 8 + ty;
        out[OUT_ZQ + (((size_t)b * CDIM + c) * HDIM + h) * WDIM + tx] = rowbuf[tx][c];
    }
}

// ---------------------------------------------------------------------------
// K6: per-code update
// ---------------------------------------------------------------------------
__global__ void __launch_bounds__(256) code_kernel(const float* __restrict__ emb,
                                                   const float* __restrict__ eprob,
                                                   float* __restrict__ out) {
    int j = blockIdx.x;
    int c = threadIdx.x;
    unsigned hcnt = g_hist[j];
    float avg = (float)hcnt * (1.0f / 16384.0f);
    float np  = __fadd_rn(__fmul_rn(eprob[j], 0.99f), __fmul_rn(avg, 0.01f));
    float t = __fmul_rn(np, 8192.0f);
    t = __fmul_rn(t, 10.0f);
    t = __fdiv_rn(t, 0.01f);
    float decay = expf(-t - 0.001f);
    float omd = __fsub_rn(1.0f, decay);
    if (c == 0) {
        out[OUT_NPROB + j] = np;
        atomicAdd(&g_ent, avg * logf(avg + 1e-10f));
        if (hcnt > 0) atomicAdd(&g_util, 1u);
    }
    int fi = (int)(g_maxkey[j] & 0xffffffffull);
    float rf = g_zf[(size_t)fi * CDIM + c];
    float e  = emb[(size_t)j * CDIM + c];
    out[OUT_NEMB + (size_t)j * CDIM + c] =
        __fadd_rn(__fmul_rn(e, omd), __fmul_rn(rf, decay));
}

// ---------------------------------------------------------------------------
// K7: finalize scalars
// ---------------------------------------------------------------------------
__global__ void fin_kernel(float* __restrict__ out) {
    float sse = g_sse;
    float mse = sse / 4194304.0f;
    out[OUT_LOSS] = __fadd_rn(__fmul_rn(0.25f, mse), mse);
    out[OUT_QERR] = sse / 16384.0f;
    out[OUT_UTIL] = (float)g_util / 8192.0f;
    out[OUT_PERP] = expf(-g_ent);
}

// ---------------------------------------------------------------------------
extern "C" void kernel_launch(void* const* d_in, const int* in_sizes, int n_in,
                              void* d_out, int out_size) {
    (void)in_sizes; (void)n_in; (void)out_size;
    const float* z     = (const float*)d_in[0];
    const float* emb   = (const float*)d_in[1];
    const float* eprob = (const float*)d_in[2];
    float* out = (float*)d_out;

    static int smem_set = 0;
    if (!smem_set) {
        cudaFuncSetAttribute(gemm_mma_kernel,
                             cudaFuncAttributeMaxDynamicSharedMemorySize,
                             GEMM_SMEM);
        smem_set = 1;
    }

    init_kernel<<<64, 256>>>();
    prep_kernel<<<BATCH * HDIM, 256>>>(z);
    e2_kernel<<<KCODE / 8, 256>>>(emb);
    gemm_mma_kernel<<<dim3(NJB, NFEAT / BM), 512, GEMM_SMEM>>>(emb);
    extras_kernel<<<256, 256>>>(emb);
    tokenfix_kernel<<<256, 256>>>(emb);
    zq_kernel<<<BATCH * HDIM, 256>>>(emb, out);
    code_kernel<<<KCODE, 256>>>(emb, eprob, out);
    fin_kernel<<<1, 1>>>(out);
}

// round 8
// speedup vs baseline: 3.8554x; 1.1685x over previous
#include <cuda_runtime.h>
#include <cuda_fp16.h>
#include <math.h>
#include <stdint.h>

// Problem constants
#define NFEAT 16384          // B*H*W = 16*32*32
#define KCODE 8192           // codebook size
#define CDIM  256            // codebook dim
#define BATCH 16
#define HDIM  32
#define WDIM  32

// Output layout (float32, concatenated in reference tuple order)
#define OUT_ZQ    0
#define OUT_LOSS  4194304
#define OUT_QERR  4194305
#define OUT_UTIL  4194306
#define OUT_PERP  4194307
#define OUT_NEMB  4194308
#define OUT_NPROB 6291460

// GEMM tiling (fp16 m16n8k16; BM64 x BN256, 256 thr, 2 CTAs/SM)
#define BM 64
#define BN 256
#define NJB (KCODE / BN)     // 32 j-blocks
#define BK 64                // fp16 k-chunk per stage
#define NKB (CDIM / BK)      // 4
#define ROWB 160             // 80 halves per row (padded) -> conflict-free LDS.64

// codebook pre-scale 2^14 (exact); epilogue rescale -2*2^-14 = -2^-13
#define ESCALE 16384.0f
#define DSCALE (-1.0f / 8192.0f)

// candidate window: > 2*ulp(256) + 2*fp16_approx_err
#define EPSB 1.2e-4f
#define MAXX (1 << 21)

// Scratch (device globals; no dynamic allocation allowed)
__device__ float              g_zf[NFEAT * CDIM];
__device__ __half             g_zh[NFEAT * CDIM];
__device__ __half             g_eh[KCODE * CDIM];   // embedding * 2^14, fp16
__device__ float              g_S[NFEAT];
__device__ float              g_e2[KCODE];
__device__ unsigned long long g_blockmin[NFEAT][NJB];
__device__ unsigned long long g_exkey[NFEAT];
__device__ unsigned int       g_extras[MAXX];
__device__ unsigned int       g_xcnt;
__device__ unsigned long long g_maxkey[KCODE];
__device__ unsigned int       g_hist[KCODE];
__device__ int                g_token[NFEAT];
__device__ float              g_sse;
__device__ float              g_ent;
__device__ unsigned int       g_util;

__device__ __forceinline__ unsigned int ford(float f) {
    unsigned int u = __float_as_uint(f);
    return u ^ ((((int)u) >> 31) | 0x80000000u);
}
__device__ __forceinline__ float unford(unsigned int u) {
    unsigned int v = (u & 0x80000000u) ? (u ^ 0x80000000u) : ~u;
    return __uint_as_float(v);
}

// exact distance on the reference fp32 grid, via compensated fp32 dot.
__device__ __forceinline__ float exact_d32(const float* __restrict__ emb,
                                           int n, int j, int lane) {
    const float* zr = g_zf + (size_t)n * CDIM;
    const float* er = emb + (size_t)j * CDIM;
    float hi = 0.0f, lo = 0.0f;
#pragma unroll
    for (int c = 0; c < CDIM / 32; c++) {
        float a = zr[lane + 32 * c], b = er[lane + 32 * c];
        float p = __fmul_rn(a, b);
        float perr = fmaf(a, b, -p);
        float s = __fadd_rn(hi, p);
        float bp = __fsub_rn(s, hi);
        float e = __fadd_rn(__fsub_rn(hi, __fsub_rn(s, bp)), __fsub_rn(p, bp));
        hi = s;
        lo = __fadd_rn(lo, __fadd_rn(e, perr));
    }
#pragma unroll
    for (int m = 16; m; m >>= 1) {
        float oh = __shfl_xor_sync(0xffffffffu, hi, m);
        float ol = __shfl_xor_sync(0xffffffffu, lo, m);
        float s = __fadd_rn(hi, oh);
        float bp = __fsub_rn(s, hi);
        float e = __fadd_rn(__fsub_rn(hi, __fsub_rn(s, bp)), __fsub_rn(oh, bp));
        hi = s;
        lo = __fadd_rn(__fadd_rn(lo, ol), e);
    }
    float dotf = __fadd_rn(hi, lo);
    return __fsub_rn(__fadd_rn(g_S[n], g_e2[j]), 2.0f * dotf);
}

// ---------------------------------------------------------------------------
__global__ void init_kernel() {
    int i = blockIdx.x * blockDim.x + threadIdx.x;
    if (i < NFEAT) g_exkey[i] = ~0ull;
    if (i < KCODE) { g_maxkey[i] = ~0ull; g_hist[i] = 0u; }
    if (i == 0) { g_sse = 0.0f; g_ent = 0.0f; g_util = 0u; g_xcnt = 0u; }
}

// ---------------------------------------------------------------------------
__global__ void __launch_bounds__(256) prep_kernel(const float* __restrict__ z) {
    __shared__ float tile[32][CDIM + 1];
    int tid = threadIdx.x;
    int tx = tid & 31, ty = tid >> 5;
    int b = blockIdx.x >> 5, h = blockIdx.x & 31;
    const float* zp = z + (size_t)b * (CDIM * HDIM * WDIM) + h * WDIM;
#pragma unroll
    for (int i = 0; i < 32; i++) {
        int c = i * 8 + ty;
        tile[tx][c] = zp[c * (HDIM * WDIM) + tx];
    }
    __syncthreads();
    int nbase = b * 1024 + h * 32;
#pragma unroll
    for (int j = 0; j < 4; j++) {
        int w = ty * 4 + j;
        int n = nbase + w;
        float s = 0.0f;
#pragma unroll
        for (int i = 0; i < 8; i++) {
            int c = tx + 32 * i;
            float v = tile[w][c];
            g_zf[(size_t)n * CDIM + c] = v;
            g_zh[(size_t)n * CDIM + c] = __float2half_rn(v);
            s += v * v;
        }
#pragma unroll
        for (int m = 16; m; m >>= 1) s += __shfl_xor_sync(0xffffffffu, s, m);
        if (tx == 0) g_S[n] = s;
    }
}

// ---------------------------------------------------------------------------
__global__ void __launch_bounds__(256) e2_kernel(const float* __restrict__ emb) {
    int tid = threadIdx.x;
    int tx = tid & 31, ty = tid >> 5;
    int j = blockIdx.x * 8 + ty;
    float s = 0.0f;
#pragma unroll
    for (int i = 0; i < 8; i++) {
        float v = emb[(size_t)j * CDIM + tx + 32 * i];
        g_eh[(size_t)j * CDIM + tx + 32 * i] = __float2half_rn(v * ESCALE);
        s += v * v;
    }
#pragma unroll
    for (int m = 16; m; m >>= 1) s += __shfl_xor_sync(0xffffffffu, s, m);
    if (tx == 0) g_e2[j] = s;
}

// ---------------------------------------------------------------------------
// K3: fp16 m16n8k16 GEMM, 256 threads (8 warps 1Mx8N, warp tile 64x32),
// 2 CTAs/SM. D values overwrite accumulators in epilogue pass 1.
// ---------------------------------------------------------------------------
#define SM_ROWKEY 0             // 64 u64  [0,512)
#define SM_COLKEY 512           // 256 u64 [512,2560)
#define SM_SS     2560          // 64 f    [2560,2816)
#define SM_E2S    2816          // 256 f   [2816,3840)
#define SM_DATA   3840
#define STAGE_A   (BM * ROWB)               // 10240
#define STAGE_B   (BN * ROWB)               // 40960
#define STAGE_SZ  (STAGE_A + STAGE_B)       // 51200
#define NSTAGE 2
#define GEMM_SMEM (SM_DATA + NSTAGE * STAGE_SZ)   // 106240

__device__ __forceinline__ void cpa16(uint32_t dst, const void* src) {
    asm volatile("cp.async.cg.shared.global [%0], [%1], 16;"
                 :: "r"(dst), "l"(src));
}

#define MMA16(d, a0, a1, a2, a3, b0, b1)                                     \
    asm volatile(                                                            \
        "mma.sync.aligned.m16n8k16.row.col.f32.f16.f16.f32 "                 \
        "{%0,%1,%2,%3},{%4,%5,%6,%7},{%8,%9},{%0,%1,%2,%3};"                 \
        : "+f"(d[0]), "+f"(d[1]), "+f"(d[2]), "+f"(d[3])                     \
        : "r"(a0), "r"(a1), "r"(a2), "r"(a3), "r"(b0), "r"(b1))

extern __shared__ char dynsmem[];

__global__ void __launch_bounds__(256, 2)
gemm_mma_kernel(const float* __restrict__ emb) {
    const int tid  = threadIdx.x;
    const int lane = tid & 31;
    const int wn   = tid >> 5;      // warp 0..7 = N split
    const int gid  = lane >> 2;     // 0..7
    const int tig  = lane & 3;      // 0..3
    const int m0   = blockIdx.y * BM;
    const int j0   = blockIdx.x * BN;

    unsigned long long* rowkey = (unsigned long long*)(dynsmem + SM_ROWKEY);
    unsigned long long* colkey = (unsigned long long*)(dynsmem + SM_COLKEY);
    float* Ss  = (float*)(dynsmem + SM_SS);
    float* e2s = (float*)(dynsmem + SM_E2S);

    uint32_t smbase;
    asm("{ .reg .u64 t; cvta.to.shared.u64 t, %1; cvt.u32.u64 %0, t; }"
        : "=r"(smbase) : "l"(dynsmem));

    // staging: rows t8, t8+32, ... ; 8 x 16B segments per row (BK=64 halves)
    const int t8 = tid >> 3;            // 0..31
    const int c8 = tid & 7;             // 0..7
    const __half* gA0 = g_zh + (size_t)(m0 + t8) * CDIM + c8 * 8;
    const __half* gB0 = g_eh + (size_t)(j0 + t8) * CDIM + c8 * 8;
    const uint32_t dA0 = smbase + SM_DATA + t8 * ROWB + c8 * 16;
    const uint32_t dB0 = smbase + SM_DATA + STAGE_A + t8 * ROWB + c8 * 16;

    auto load_kb = [&](int s, int kb) {
        uint32_t so = s * STAGE_SZ;
        const __half* ga = gA0 + kb * BK;
        const __half* gb = gB0 + kb * BK;
#pragma unroll
        for (int i = 0; i < 2; i++)
            cpa16(dA0 + so + i * 32 * ROWB, ga + (size_t)i * 32 * CDIM);
#pragma unroll
        for (int i = 0; i < 8; i++)
            cpa16(dB0 + so + i * 32 * ROWB, gb + (size_t)i * 32 * CDIM);
    };

    if (tid < 64) { rowkey[tid] = ~0ull; Ss[tid] = g_S[m0 + tid]; }
    colkey[tid] = ~0ull;
    e2s[tid] = g_e2[j0 + tid];

    load_kb(0, 0);
    asm volatile("cp.async.commit_group;" ::: "memory");

    float acc[4][4][4];
#pragma unroll
    for (int nt = 0; nt < 4; nt++)
#pragma unroll
        for (int mt = 0; mt < 4; mt++)
#pragma unroll
            for (int c = 0; c < 4; c++) acc[nt][mt][c] = 0.0f;

    // fragment bases in uint2 (8B = 4 halves) units
    const int aBase2 = gid * (ROWB / 8) + tig;
    const int bBase2 = (wn * 32 + gid) * (ROWB / 8) + tig;

#pragma unroll 1
    for (int kb = 0; kb < NKB; kb++) {
        if (kb + 1 < NKB) {
            load_kb((kb + 1) & 1, kb + 1);
            asm volatile("cp.async.commit_group;" ::: "memory");
            asm volatile("cp.async.wait_group 1;" ::: "memory");
        } else {
            asm volatile("cp.async.wait_group 0;" ::: "memory");
        }
        __syncthreads();

        const uint2* Af2 =
            (const uint2*)(dynsmem + SM_DATA + (kb & 1) * STAGE_SZ);
        const uint2* Bf2 = Af2 + STAGE_A / 8;

#pragma unroll
        for (int ks = 0; ks < BK / 16; ks++) {        // 4 k16-steps
            const int ko = ks * 4;
            uint2 alo[4], ahi[4], bv[4];
#pragma unroll
            for (int mt = 0; mt < 4; mt++) {
                int o = aBase2 + mt * 16 * (ROWB / 8) + ko;
                alo[mt] = Af2[o];
                ahi[mt] = Af2[o + 8 * (ROWB / 8)];
            }
#pragma unroll
            for (int nt = 0; nt < 4; nt++)
                bv[nt] = Bf2[bBase2 + nt * 8 * (ROWB / 8) + ko];
#pragma unroll
            for (int nt = 0; nt < 4; nt++)
#pragma unroll
                for (int mt = 0; mt < 4; mt++)
                    MMA16(acc[nt][mt], alo[mt].x, ahi[mt].x,
                          alo[mt].y, ahi[mt].y, bv[nt].x, bv[nt].y);
        }
        __syncthreads();
    }

    // ---- epilogue pass 1: d -> acc (in place), argmin/argmax ----
    float S_lo[4], S_hi[4];
#pragma unroll
    for (int mt = 0; mt < 4; mt++) {
        S_lo[mt] = Ss[mt * 16 + gid];
        S_hi[mt] = Ss[mt * 16 + gid + 8];
    }
    float bd_lo[4], bd_hi[4];
    int   bj_lo[4], bj_hi[4];
#pragma unroll
    for (int mt = 0; mt < 4; mt++) {
        bd_lo[mt] = __int_as_float(0x7f800000); bj_lo[mt] = 0;
        bd_hi[mt] = __int_as_float(0x7f800000); bj_hi[mt] = 0;
    }

#pragma unroll
    for (int nt = 0; nt < 4; nt++) {
        const int ca = wn * 32 + nt * 8 + 2 * tig;
        const float e2a = e2s[ca], e2b = e2s[ca + 1];
        const int ja = j0 + ca;
        float cva = __int_as_float(0xff800000), cvb = cva;   // -inf
        int cia = 0, cib = 0;
#pragma unroll
        for (int mt = 0; mt < 4; mt++) {
            const int rlo = m0 + mt * 16 + gid;
            float d00 = fmaf(acc[nt][mt][0], DSCALE, S_lo[mt] + e2a);
            float d01 = fmaf(acc[nt][mt][1], DSCALE, S_lo[mt] + e2b);
            float d10 = fmaf(acc[nt][mt][2], DSCALE, S_hi[mt] + e2a);
            float d11 = fmaf(acc[nt][mt][3], DSCALE, S_hi[mt] + e2b);
            acc[nt][mt][0] = d00; acc[nt][mt][1] = d01;
            acc[nt][mt][2] = d10; acc[nt][mt][3] = d11;
            if (d00 < bd_lo[mt]) { bd_lo[mt] = d00; bj_lo[mt] = ja; }
            if (d01 < bd_lo[mt]) { bd_lo[mt] = d01; bj_lo[mt] = ja + 1; }
            if (d10 < bd_hi[mt]) { bd_hi[mt] = d10; bj_hi[mt] = ja; }
            if (d11 < bd_hi[mt]) { bd_hi[mt] = d11; bj_hi[mt] = ja + 1; }
            if (d00 > cva) { cva = d00; cia = rlo; }
            if (d10 > cva) { cva = d10; cia = rlo + 8; }
            if (d01 > cvb) { cvb = d01; cib = rlo; }
            if (d11 > cvb) { cvb = d11; cib = rlo + 8; }
        }
#pragma unroll
        for (int off = 4; off < 32; off <<= 1) {
            float ov = __shfl_xor_sync(0xffffffffu, cva, off);
            int   oi = __shfl_xor_sync(0xffffffffu, cia, off);
            if (ov > cva || (ov == cva && oi < cia)) { cva = ov; cia = oi; }
            ov = __shfl_xor_sync(0xffffffffu, cvb, off);
            oi = __shfl_xor_sync(0xffffffffu, cib, off);
            if (ov > cvb || (ov == cvb && oi < cib)) { cvb = ov; cib = oi; }
        }
        if (gid == 0) {
            atomicMin(&colkey[ca],
                      (((unsigned long long)(~ford(cva))) << 32) | (unsigned)cia);
            atomicMin(&colkey[ca + 1],
                      (((unsigned long long)(~ford(cvb))) << 32) | (unsigned)cib);
        }
    }
#pragma unroll
    for (int mt = 0; mt < 4; mt++) {
        unsigned long long klo =
            (((unsigned long long)ford(bd_lo[mt])) << 32) | (unsigned)bj_lo[mt];
        unsigned long long khi =
            (((unsigned long long)ford(bd_hi[mt])) << 32) | (unsigned)bj_hi[mt];
#pragma unroll
        for (int off = 1; off < 4; off <<= 1) {
            klo = min(klo, __shfl_xor_sync(0xffffffffu, klo, off));
            khi = min(khi, __shfl_xor_sync(0xffffffffu, khi, off));
        }
        if (tig == 0) {
            atomicMin(&rowkey[mt * 16 + gid], klo);
            atomicMin(&rowkey[mt * 16 + gid + 8], khi);
        }
    }
    __syncthreads();

    if (tid < 64) g_blockmin[m0 + tid][blockIdx.x] = rowkey[tid];
    atomicMin(&g_maxkey[j0 + tid], colkey[tid]);

    // ---- epilogue pass 2: append near-tie candidates (d cached in acc) ----
#pragma unroll
    for (int mt = 0; mt < 4; mt++) {
        const int rl = mt * 16 + gid;
        const int rh = rl + 8;
        const unsigned long long rkl = rowkey[rl];
        const unsigned long long rkh = rowkey[rh];
        const float vl = unford((unsigned)(rkl >> 32)) + EPSB;
        const float vh = unford((unsigned)(rkh >> 32)) + EPSB;
#pragma unroll
        for (int nt = 0; nt < 4; nt++) {
            const int ca = wn * 32 + nt * 8 + 2 * tig;
            const unsigned ja = (unsigned)(j0 + ca);
            float d00 = acc[nt][mt][0];
            float d01 = acc[nt][mt][1];
            float d10 = acc[nt][mt][2];
            float d11 = acc[nt][mt][3];
            if (d00 < vl) {
                unsigned long long k = (((unsigned long long)ford(d00)) << 32) | ja;
                if (k != rkl) {
                    unsigned slot = atomicAdd(&g_xcnt, 1u);
                    if (slot < MAXX)
                        g_extras[slot] = ((unsigned)(m0 + rl) << 13) | ja;
                }
            }
            if (d01 < vl) {
                unsigned long long k = (((unsigned long long)ford(d01)) << 32) | (ja + 1);
                if (k != rkl) {
                    unsigned slot = atomicAdd(&g_xcnt, 1u);
                    if (slot < MAXX)
                        g_extras[slot] = ((unsigned)(m0 + rl) << 13) | (ja + 1);
                }
            }
            if (d10 < vh) {
                unsigned long long k = (((unsigned long long)ford(d10)) << 32) | ja;
                if (k != rkh) {
                    unsigned slot = atomicAdd(&g_xcnt, 1u);
                    if (slot < MAXX)
                        g_extras[slot] = ((unsigned)(m0 + rh) << 13) | ja;
                }
            }
            if (d11 < vh) {
                unsigned long long k = (((unsigned long long)ford(d11)) << 32) | (ja + 1);
                if (k != rkh) {
                    unsigned slot = atomicAdd(&g_xcnt, 1u);
                    if (slot < MAXX)
                        g_extras[slot] = ((unsigned)(m0 + rh) << 13) | (ja + 1);
                }
            }
        }
    }
}

// ---------------------------------------------------------------------------
__global__ void __launch_bounds__(256) extras_kernel(const float* __restrict__ emb) {
    const unsigned cnt = min(g_xcnt, (unsigned)MAXX);
    const int lane = threadIdx.x & 31;
    const int wid = (blockIdx.x * blockDim.x + threadIdx.x) >> 5;
    const int nw = (gridDim.x * blockDim.x) >> 5;
    for (unsigned i = wid; i < cnt; i += nw) {
        unsigned e = g_extras[i];
        int n = e >> 13;
        int j = e & 8191;
        float d32 = exact_d32(emb, n, j, lane);
        unsigned long long key =
            (((unsigned long long)ford(d32)) << 32) | (unsigned)j;
        if (lane == 0) atomicMin(&g_exkey[n], key);
    }
}

// ---------------------------------------------------------------------------
__global__ void __launch_bounds__(256) tokenfix_kernel(const float* __restrict__ emb) {
    const int lane = threadIdx.x & 31;
    const int wid = (blockIdx.x * blockDim.x + threadIdx.x) >> 5;
    const int nw = (gridDim.x * blockDim.x) >> 5;
    for (int n = wid; n < NFEAT; n += nw) {
        unsigned long long k = g_blockmin[n][lane];   // NJB == 32
        unsigned long long gm = k;
#pragma unroll
        for (int m = 16; m; m >>= 1)
            gm = min(gm, __shfl_xor_sync(0xffffffffu, gm, m));
        float thresh = unford((unsigned)(gm >> 32)) + EPSB;
        bool cand = unford((unsigned)(k >> 32)) < thresh;
        unsigned bal = __ballot_sync(0xffffffffu, cand);
        unsigned long long ex = g_exkey[n];
        unsigned tok;
        if (__popc(bal) == 1 && ex == ~0ull) {
            tok = (unsigned)(gm & 0xffffffffull);
        } else {
            unsigned long long best = ex;
            unsigned b = bal;
            while (b) {
                int src = __ffs(b) - 1;
                b &= b - 1;
                unsigned jj = __shfl_sync(0xffffffffu,
                                          (unsigned)(k & 0xffffffffull), src);
                float d32 = exact_d32(emb, n, (int)jj, lane);
                unsigned long long key =
                    (((unsigned long long)ford(d32)) << 32) | jj;
                best = min(best, key);
            }
            tok = (unsigned)(best & 0xffffffffull);
        }
        if (lane == 0) {
            g_token[n] = (int)tok;
            atomicAdd(&g_hist[tok], 1u);
        }
    }
}

// ---------------------------------------------------------------------------
__global__ void __launch_bounds__(256) zq_kernel(const float* __restrict__ emb,
                                                 float* __restrict__ out) {
    __shared__ float rowbuf[32][CDIM + 1];
    __shared__ int stok[32];
    __shared__ float red[8];
    int tid = threadIdx.x;
    int b = blockIdx.x >> 5, h = blockIdx.x & 31;
    int nbase = b * 1024 + h * 32;
    if (tid < 32) stok[tid] = g_token[nbase + tid];
    __syncthreads();
    float acc = 0.0f;
#pragma unroll 4
    for (int w = 0; w < 32; w++) {
        float v  = emb[(size_t)stok[w] * CDIM + tid];
        float zv = g_zf[(size_t)(nbase + w) * CDIM + tid];
        float diff = __fsub_rn(v, zv);
        acc = fmaf(diff, diff, acc);
        rowbuf[w][tid] = __fadd_rn(zv, diff);
    }
    float s = acc;
#pragma unroll
    for (int m = 16; m; m >>= 1) s += __shfl_xor_sync(0xffffffffu, s, m);
    if ((tid & 31) == 0) red[tid >> 5] = s;
    __syncthreads();
    if (tid == 0) {
        float t = 0.0f;
#pragma unroll
        for (int i = 0; i < 8; i++) t += red[i];
        atomicAdd(&g_sse, t);
    }
    int tx = tid & 31, ty = tid >> 5;
#pragma unroll
    for (int i = 0; i < 32; i++) {
        int c = i * 8 + ty;
        out[OUT_ZQ + (((size_t)b * CDIM + c) * HDIM + h) * WDIM + tx] = rowbuf[tx][c];
    }
}

// ---------------------------------------------------------------------------
__global__ void __launch_bounds__(256) code_kernel(const float* __restrict__ emb,
                                                   const float* __restrict__ eprob,
                                                   float* __restrict__ out) {
    int j = blockIdx.x;
    int c = threadIdx.x;
    unsigned hcnt = g_hist[j];
    float avg = (float)hcnt * (1.0f / 16384.0f);
    float np  = __fadd_rn(__fmul_rn(eprob[j], 0.99f), __fmul_rn(avg, 0.01f));
    float t = __fmul_rn(np, 8192.0f);
    t = __fmul_rn(t, 10.0f);
    t = __fdiv_rn(t, 0.01f);
    float decay = expf(-t - 0.001f);
    float omd = __fsub_rn(1.0f, decay);
    if (c == 0) {
        out[OUT_NPROB + j] = np;
        atomicAdd(&g_ent, avg * logf(avg + 1e-10f));
        if (hcnt > 0) atomicAdd(&g_util, 1u);
    }
    int fi = (int)(g_maxkey[j] & 0xffffffffull);
    float rf = g_zf[(size_t)fi * CDIM + c];
    float e  = emb[(size_t)j * CDIM + c];
    out[OUT_NEMB + (size_t)j * CDIM + c] =
        __fadd_rn(__fmul_rn(e, omd), __fmul_rn(rf, decay));
}

// ---------------------------------------------------------------------------
__global__ void fin_kernel(float* __restrict__ out) {
    float sse = g_sse;
    float mse = sse / 4194304.0f;
    out[OUT_LOSS] = __fadd_rn(__fmul_rn(0.25f, mse), mse);
    out[OUT_QERR] = sse / 16384.0f;
    out[OUT_UTIL] = (float)g_util / 8192.0f;
    out[OUT_PERP] = expf(-g_ent);
}

// ---------------------------------------------------------------------------
extern "C" void kernel_launch(void* const* d_in, const int* in_sizes, int n_in,
                              void* d_out, int out_size) {
    (void)in_sizes; (void)n_in; (void)out_size;
    const float* z     = (const float*)d_in[0];
    const float* emb   = (const float*)d_in[1];
    const float* eprob = (const float*)d_in[2];
    float* out = (float*)d_out;

    static int smem_set = 0;
    if (!smem_set) {
        cudaFuncSetAttribute(gemm_mma_kernel,
                             cudaFuncAttributeMaxDynamicSharedMemorySize,
                             GEMM_SMEM);
        smem_set = 1;
    }

    init_kernel<<<64, 256>>>();
    prep_kernel<<<BATCH * HDIM, 256>>>(z);
    e2_kernel<<<KCODE / 8, 256>>>(emb);
    gemm_mma_kernel<<<dim3(NJB, NFEAT / BM), 256, GEMM_SMEM>>>(emb);
    extras_kernel<<<256, 256>>>(emb);
    tokenfix_kernel<<<256, 256>>>(emb);
    zq_kernel<<<BATCH * HDIM, 256>>>(emb, out);
    code_kernel<<<KCODE, 256>>>(emb, eprob, out);
    fin_kernel<<<1, 1>>>(out);
}